// round 1
// baseline (speedup 1.0000x reference)
#include <cuda_runtime.h>
#include <math.h>
#include <stdint.h>

#define B    32
#define H    512
#define V    32000
#define TIN  50
#define TOUT 50
#define NPB  125      // projection blocks
#define VPB  256      // v-columns per projection block

#define OFF_HT   ((size_t)B * V * TOUT)          // 51,200,000
#define OFF_ATTN (OFF_HT + (size_t)B * H)        // 51,216,384

// ---------------- device scratch (static, allowed) ----------------
__device__ float g_zbuf[(size_t)TOUT * B * V];   // raw logits, 204.8 MB
__device__ float g_pmax[NPB][B];
__device__ float g_psum[NPB][B];
__device__ int   g_pidx[NPB][B];
__device__ float g_logZ[TOUT][B];
__device__ float g_h[2][B][H];
__device__ float g_xc[B][H];
__device__ float g_gh[B][3 * H];
__device__ float g_attnx[B][H];
__device__ float g_cattn[B][H];

// ---------------- f32x2 helpers ----------------
__device__ __forceinline__ unsigned long long fma2(unsigned long long a,
                                                   unsigned long long b,
                                                   unsigned long long c) {
    unsigned long long d;
    asm("fma.rn.f32x2 %0, %1, %2, %3;" : "=l"(d) : "l"(a), "l"(b), "l"(c));
    return d;
}
__device__ __forceinline__ void upk(unsigned long long v, float& lo, float& hi) {
    asm("mov.b64 {%0, %1}, %2;" : "=f"(lo), "=f"(hi) : "l"(v));
}

// ============================================================================
// P1: attn_x = sum_t encoder_out ; h0 = 0 ; attn output = ones
// ============================================================================
extern "C" __global__ void p1_kernel(const float* __restrict__ enc,
                                     float* __restrict__ d_out) {
    int gid  = blockIdx.x * blockDim.x + threadIdx.x;
    int nthr = gridDim.x * blockDim.x;
    for (int i = gid; i < B * H; i += nthr) {
        int b = i >> 9, k = i & 511;
        g_h[0][b][k] = 0.f;
        float s = 0.f;
        #pragma unroll 5
        for (int tt = 0; tt < TIN; tt++) s += enc[((size_t)b * TIN + tt) * H + k];
        g_attnx[b][k] = s;
    }
    float4 one4 = make_float4(1.f, 1.f, 1.f, 1.f);
    float4* dst = reinterpret_cast<float4*>(d_out + OFF_ATTN);
    size_t n4 = (size_t)TOUT * B * TIN * H / 4;
    for (size_t i = gid; i < n4; i += nthr) dst[i] = one4;
}

// ============================================================================
// P2: c_attn[b][o] = attn_x[b] . W_comb[o][H:2H] + b_comb[o]
// ============================================================================
extern "C" __global__ void __launch_bounds__(256)
p2_kernel(const float* __restrict__ W_comb, const float* __restrict__ b_comb) {
    __shared__ float s_in[B][128];
    int tid = threadIdx.x;
    int ob = blockIdx.x * 32;
    int o = tid & 31, bq = tid >> 5;
    float acc[4] = {0.f, 0.f, 0.f, 0.f};
    const float* wrow = W_comb + (size_t)(ob + o) * (2 * H) + H;
    for (int kc = 0; kc < H; kc += 128) {
        for (int i = tid; i < B * 128; i += 256) {
            int b = i >> 7, k = i & 127;
            s_in[b][k] = g_attnx[b][kc + k];
        }
        __syncthreads();
        #pragma unroll 4
        for (int k = 0; k < 128; k += 4) {
            float4 w = *reinterpret_cast<const float4*>(wrow + kc + k);
            #pragma unroll
            for (int j = 0; j < 4; j++) {
                int b = bq + 8 * j;
                float4 xv = *reinterpret_cast<const float4*>(&s_in[b][k]);
                acc[j] += xv.x * w.x + xv.y * w.y + xv.z * w.z + xv.w * w.w;
            }
        }
        __syncthreads();
    }
    #pragma unroll
    for (int j = 0; j < 4; j++) {
        int b = bq + 8 * j;
        g_cattn[b][ob + o] = acc[j] + b_comb[ob + o];
    }
}

// ============================================================================
// KA: (t>0: merge prev-step partials -> tok[t], logZ[t-1])
//     then xc = relu(x @ Wcomb_x^T + c_attn)  (blocks 0..15)
//          gh = h @ W_hh^T + b_hh             (blocks 16..63)
// ============================================================================
extern "C" __global__ void __launch_bounds__(256)
ka_kernel(int t, int cur, const float* __restrict__ emb, const int* __restrict__ y,
          const float* __restrict__ W_comb, const float* __restrict__ W_hh,
          const float* __restrict__ b_hh) {
    __shared__ int   s_tok[B];
    __shared__ float sm_m[8][B], sm_s[8][B], sm_av[8][B];
    __shared__ int   sm_ai[8][B];
    __shared__ float s_in[B][128];

    int tid = threadIdx.x;
    if (t > 0) {
        int b = tid & 31, part = tid >> 5;
        float m = -INFINITY, s = 0.f, av = -INFINITY;
        int ai = 0x7fffffff;
        for (int i = part; i < NPB; i += 8) {
            float pm = g_pmax[i][b];
            float ps = g_psum[i][b];
            int   pi = g_pidx[i][b];
            if (pm > m) { s = s * expf(m - pm) + ps; m = pm; }
            else        { s += ps * expf(pm - m); }
            if (pm > av || (pm == av && pi < ai)) { av = pm; ai = pi; }
        }
        sm_m[part][b] = m; sm_s[part][b] = s; sm_av[part][b] = av; sm_ai[part][b] = ai;
        __syncthreads();
        if (tid < B) {
            float M = -INFINITY, S = 0.f, AV = -INFINITY;
            int AI = 0x7fffffff;
            #pragma unroll
            for (int p = 0; p < 8; p++) {
                float pm = sm_m[p][tid], ps = sm_s[p][tid];
                if (pm > M) { S = S * expf(M - pm) + ps; M = pm; }
                else        { S += ps * expf(pm - M); }
                float v2 = sm_av[p][tid]; int i2 = sm_ai[p][tid];
                if (v2 > AV || (v2 == AV && i2 < AI)) { AV = v2; AI = i2; }
            }
            s_tok[tid] = AI;
            if (blockIdx.x == 0) g_logZ[t - 1][tid] = M + logf(S);
        }
        __syncthreads();
    } else {
        if (tid < B) s_tok[tid] = y[tid * TOUT];  // y[b][0]
        __syncthreads();
    }

    int ob = blockIdx.x * 32;
    bool is_xc = (ob < H);
    int o = tid & 31, bq = tid >> 5;
    float acc[4] = {0.f, 0.f, 0.f, 0.f};
    const float* wrow = is_xc ? (W_comb + (size_t)(ob + o) * (2 * H))
                              : (W_hh + (size_t)(ob - H + o) * H);
    for (int kc = 0; kc < H; kc += 128) {
        for (int i = tid; i < B * 128; i += 256) {
            int b = i >> 7, k = i & 127;
            s_in[b][k] = is_xc ? emb[(size_t)s_tok[b] * H + kc + k]
                               : g_h[cur][b][kc + k];
        }
        __syncthreads();
        #pragma unroll 4
        for (int k = 0; k < 128; k += 4) {
            float4 w = *reinterpret_cast<const float4*>(wrow + kc + k);
            #pragma unroll
            for (int j = 0; j < 4; j++) {
                int b = bq + 8 * j;
                float4 xv = *reinterpret_cast<const float4*>(&s_in[b][k]);
                acc[j] += xv.x * w.x + xv.y * w.y + xv.z * w.z + xv.w * w.w;
            }
        }
        __syncthreads();
    }
    if (is_xc) {
        #pragma unroll
        for (int j = 0; j < 4; j++) {
            int b = bq + 8 * j;
            float v0 = acc[j] + g_cattn[b][ob + o];
            g_xc[b][ob + o] = v0 > 0.f ? v0 : 0.f;
        }
    } else {
        int oc = ob - H + o;
        float bb = b_hh[oc];
        #pragma unroll
        for (int j = 0; j < 4; j++) {
            int b = bq + 8 * j;
            g_gh[b][oc] = acc[j] + bb;
        }
    }
}

// ============================================================================
// KB: gi = xc @ W_ih^T + b_ih ; GRU elementwise -> h_new
// ============================================================================
extern "C" __global__ void __launch_bounds__(256)
kb_kernel(int t, int cur, const float* __restrict__ W_ih,
          const float* __restrict__ b_ih, float* __restrict__ d_out) {
    __shared__ float s_xc[B][128];
    int tid = threadIdx.x;
    int ob = blockIdx.x * 32;
    int o = tid & 31, bq = tid >> 5;
    int oc = ob + o;
    float a0[4] = {0.f, 0.f, 0.f, 0.f};
    float a1[4] = {0.f, 0.f, 0.f, 0.f};
    float a2[4] = {0.f, 0.f, 0.f, 0.f};
    const float* w0 = W_ih + (size_t)oc * H;
    const float* w1 = W_ih + (size_t)(oc + H) * H;
    const float* w2 = W_ih + (size_t)(oc + 2 * H) * H;
    for (int kc = 0; kc < H; kc += 128) {
        for (int i = tid; i < B * 128; i += 256) {
            int b = i >> 7, k = i & 127;
            s_xc[b][k] = g_xc[b][kc + k];
        }
        __syncthreads();
        #pragma unroll 2
        for (int k = 0; k < 128; k += 4) {
            float4 u0 = *reinterpret_cast<const float4*>(w0 + kc + k);
            float4 u1 = *reinterpret_cast<const float4*>(w1 + kc + k);
            float4 u2 = *reinterpret_cast<const float4*>(w2 + kc + k);
            #pragma unroll
            for (int j = 0; j < 4; j++) {
                int b = bq + 8 * j;
                float4 xv = *reinterpret_cast<const float4*>(&s_xc[b][k]);
                a0[j] += xv.x * u0.x + xv.y * u0.y + xv.z * u0.z + xv.w * u0.w;
                a1[j] += xv.x * u1.x + xv.y * u1.y + xv.z * u1.z + xv.w * u1.w;
                a2[j] += xv.x * u2.x + xv.y * u2.y + xv.z * u2.z + xv.w * u2.w;
            }
        }
        __syncthreads();
    }
    int nxt = cur ^ 1;
    float bi0 = b_ih[oc], bi1 = b_ih[oc + H], bi2 = b_ih[oc + 2 * H];
    #pragma unroll
    for (int j = 0; j < 4; j++) {
        int b = bq + 8 * j;
        float ir  = a0[j] + bi0;
        float iz  = a1[j] + bi1;
        float inn = a2[j] + bi2;
        float ghr = g_gh[b][oc];
        float ghz = g_gh[b][oc + H];
        float ghn = g_gh[b][oc + 2 * H];
        float r  = 1.f / (1.f + expf(-(ir + ghr)));
        float zz = 1.f / (1.f + expf(-(iz + ghz)));
        float n  = tanhf(inn + r * ghn);
        float hp = g_h[cur][b][oc];
        float hn = (1.f - zz) * n + zz * hp;
        g_h[nxt][b][oc] = hn;
        if (t == TOUT - 1) d_out[OFF_HT + (size_t)b * H + oc] = hn;
    }
}

// ============================================================================
// KC: z = h_new @ W_out^T + b_out   (f32x2 packed over k-pairs)
//     writes raw z to zbuf[t][b][v] + per-block (max, argmax, sumexp) partials
// ============================================================================
extern "C" __global__ void __launch_bounds__(256)
kc_kernel(int t, int hidx, const float* __restrict__ W_out,
          const float* __restrict__ b_out) {
    __shared__ ulonglong2 wsm[8][257];  // [kq][v]  (+1 pad per row)
    __shared__ ulonglong2 hsm[32][8];   // [b][kq]
    int tid = threadIdx.x;
    int vg = tid & 31, bg = tid >> 5;
    int vbase = blockIdx.x * VPB;

    unsigned long long acc[4][8];
    #pragma unroll
    for (int j = 0; j < 4; j++)
        #pragma unroll
        for (int i = 0; i < 8; i++) acc[j][i] = 0ull;

    const float* hptr = &g_h[hidx][0][0];
    for (int kc = 0; kc < H; kc += 32) {
        {
            int b = tid >> 3, kq = tid & 7;
            hsm[b][kq] = *reinterpret_cast<const ulonglong2*>(
                hptr + (size_t)b * H + kc + 4 * kq);
        }
        #pragma unroll
        for (int p = 0; p < 8; p++) {
            int idx = p * 256 + tid;
            int vl = idx >> 3, kq = idx & 7;
            wsm[kq][vl] = *reinterpret_cast<const ulonglong2*>(
                W_out + (size_t)(vbase + vl) * H + kc + 4 * kq);
        }
        __syncthreads();
        #pragma unroll
        for (int kq = 0; kq < 8; kq++) {
            ulonglong2 hv[4];
            #pragma unroll
            for (int j = 0; j < 4; j++) hv[j] = hsm[bg + 8 * j][kq];
            #pragma unroll
            for (int i = 0; i < 8; i++) {
                ulonglong2 wv = wsm[kq][vg + 32 * i];
                #pragma unroll
                for (int j = 0; j < 4; j++) {
                    acc[j][i] = fma2(hv[j].x, wv.x, acc[j][i]);
                    acc[j][i] = fma2(hv[j].y, wv.y, acc[j][i]);
                }
            }
        }
        __syncthreads();
    }

    #pragma unroll
    for (int j = 0; j < 4; j++) {
        int b = bg + 8 * j;
        float zv[8];
        float lmax = -INFINITY;
        int lidx = 0;
        #pragma unroll
        for (int i = 0; i < 8; i++) {
            float lo, hi;
            upk(acc[j][i], lo, hi);
            int v = vbase + vg + 32 * i;
            float z = lo + hi + b_out[v];
            zv[i] = z;
            g_zbuf[((size_t)t * B + b) * V + v] = z;
            if (z > lmax) { lmax = z; lidx = v; }  // first occurrence (v ascending)
        }
        float wm = lmax;
        int wi = lidx;
        #pragma unroll
        for (int off = 16; off; off >>= 1) {
            float om = __shfl_xor_sync(0xffffffffu, wm, off);
            int   oi = __shfl_xor_sync(0xffffffffu, wi, off);
            if (om > wm || (om == wm && oi < wi)) { wm = om; wi = oi; }
        }
        float ls = 0.f;
        #pragma unroll
        for (int i = 0; i < 8; i++) ls += expf(zv[i] - wm);
        #pragma unroll
        for (int off = 16; off; off >>= 1)
            ls += __shfl_xor_sync(0xffffffffu, ls, off);
        if (vg == 0) {
            g_pmax[blockIdx.x][b] = wm;
            g_psum[blockIdx.x][b] = ls;
            g_pidx[blockIdx.x][b] = wi;
        }
    }
}

// ============================================================================
// E1: final logZ for t = TOUT-1
// ============================================================================
extern "C" __global__ void __launch_bounds__(256) e1_kernel() {
    __shared__ float sm_m[8][B], sm_s[8][B];
    int tid = threadIdx.x;
    int b = tid & 31, part = tid >> 5;
    float m = -INFINITY, s = 0.f;
    for (int i = part; i < NPB; i += 8) {
        float pm = g_pmax[i][b], ps = g_psum[i][b];
        if (pm > m) { s = s * expf(m - pm) + ps; m = pm; }
        else        { s += ps * expf(pm - m); }
    }
    sm_m[part][b] = m; sm_s[part][b] = s;
    __syncthreads();
    if (tid < B) {
        float M = -INFINITY, S = 0.f;
        #pragma unroll
        for (int p = 0; p < 8; p++) {
            float pm = sm_m[p][tid], ps = sm_s[p][tid];
            if (pm > M) { S = S * expf(M - pm) + ps; M = pm; }
            else        { S += ps * expf(pm - M); }
        }
        g_logZ[TOUT - 1][tid] = M + logf(S);
    }
}

// ============================================================================
// E2: out[b][v][t] = z[t][b][v] - logZ[t][b]   (smem-tiled transpose)
// ============================================================================
extern "C" __global__ void __launch_bounds__(256)
e2_kernel(float* __restrict__ d_out) {
    __shared__ float s_z[128][52];
    __shared__ float s_lz[TOUT];
    int b = blockIdx.y;
    int v0 = blockIdx.x * 128;
    int tid = threadIdx.x;
    if (tid < TOUT) s_lz[tid] = g_logZ[tid][b];
    __syncthreads();
    for (int j = tid; j < 128 * TOUT; j += 256) {
        int tt = j >> 7, vl = j & 127;
        s_z[vl][tt] = g_zbuf[((size_t)tt * B + b) * V + v0 + vl] - s_lz[tt];
    }
    __syncthreads();
    size_t base = ((size_t)b * V + v0) * TOUT;
    for (int j = tid; j < 128 * TOUT; j += 256) {
        int vl = j / TOUT, tt = j % TOUT;
        d_out[base + j] = s_z[vl][tt];
    }
}

// ============================================================================
extern "C" void kernel_launch(void* const* d_in, const int* in_sizes, int n_in,
                              void* d_out_v, int out_size) {
    const float* enc    = (const float*)d_in[0];
    const int*   y      = (const int*)d_in[1];
    const float* emb    = (const float*)d_in[2];
    // d_in[3..6]: W_fc, b_fc, W_fc1, W_fc2 — dead (softmax over singleton axis)
    const float* W_comb = (const float*)d_in[7];
    const float* b_comb = (const float*)d_in[8];
    const float* W_ih   = (const float*)d_in[9];
    const float* W_hh   = (const float*)d_in[10];
    const float* b_ih   = (const float*)d_in[11];
    const float* b_hh   = (const float*)d_in[12];
    const float* W_out  = (const float*)d_in[13];
    const float* b_out  = (const float*)d_in[14];
    float* d_out = (float*)d_out_v;

    p1_kernel<<<512, 256>>>(enc, d_out);
    p2_kernel<<<16, 256>>>(W_comb, b_comb);
    for (int t = 0; t < TOUT; t++) {
        int cur = t & 1;
        ka_kernel<<<64, 256>>>(t, cur, emb, y, W_comb, W_hh, b_hh);
        kb_kernel<<<16, 256>>>(t, cur, W_ih, b_ih, d_out);
        kc_kernel<<<NPB, 256>>>(t, cur ^ 1, W_out, b_out);
    }
    e1_kernel<<<1, 256>>>();
    e2_kernel<<<dim3(V / 128, B), 256>>>(d_out);
}

// round 2
// speedup vs baseline: 1.4790x; 1.4790x over previous
#include <cuda_runtime.h>
#include <math.h>
#include <stdint.h>
#include <limits.h>

#define B    32
#define H    512
#define V    32000
#define TIN  50
#define TOUT 50
#define NPB  250      // projection blocks (V / VPB)
#define VPB  128      // v-columns per projection block

#define OFF_HT   ((size_t)B * V * TOUT)          // 51,200,000
#define OFF_ATTN (OFF_HT + (size_t)B * H)        // 51,216,384

// ---------------- device scratch (static, allowed) ----------------
__device__ float g_zbuf[(size_t)TOUT * B * V];   // raw logits, 204.8 MB
__device__ float g_pmax[NPB][B];
__device__ float g_psum[NPB][B];
__device__ int   g_pidx[NPB][B];
__device__ float g_logZ[TOUT][B];
__device__ float g_h[2][B][H];
__device__ float g_xc[B][H];
__device__ float g_gh[B][3 * H];
__device__ float g_attnx[B][H];
__device__ float g_cattn[B][H];

// ---------------- helpers ----------------
__device__ __forceinline__ unsigned long long fma2(unsigned long long a,
                                                   unsigned long long b,
                                                   unsigned long long c) {
    unsigned long long d;
    asm("fma.rn.f32x2 %0, %1, %2, %3;" : "=l"(d) : "l"(a), "l"(b), "l"(c));
    return d;
}
__device__ __forceinline__ void upk(unsigned long long v, float& lo, float& hi) {
    asm("mov.b64 {%0, %1}, %2;" : "=f"(lo), "=f"(hi) : "l"(v));
}
__device__ __forceinline__ unsigned sm_u32(const void* p) {
    return (unsigned)__cvta_generic_to_shared(p);
}
__device__ __forceinline__ void cpa16(unsigned d, const void* s) {
    asm volatile("cp.async.cg.shared.global [%0], [%1], 16;" :: "r"(d), "l"(s));
}

// ============================================================================
// P1: attn_x = sum_t encoder_out ; h0 = 0 ; attn output = ones
// ============================================================================
extern "C" __global__ void p1_kernel(const float* __restrict__ enc,
                                     float* __restrict__ d_out) {
    int gid  = blockIdx.x * blockDim.x + threadIdx.x;
    int nthr = gridDim.x * blockDim.x;
    for (int i = gid; i < B * H; i += nthr) {
        int b = i >> 9, k = i & 511;
        g_h[0][b][k] = 0.f;
        float s = 0.f;
        #pragma unroll 5
        for (int tt = 0; tt < TIN; tt++) s += enc[((size_t)b * TIN + tt) * H + k];
        g_attnx[b][k] = s;
    }
    float4 one4 = make_float4(1.f, 1.f, 1.f, 1.f);
    float4* dst = reinterpret_cast<float4*>(d_out + OFF_ATTN);
    size_t n4 = (size_t)TOUT * B * TIN * H / 4;
    for (size_t i = gid; i < n4; i += nthr) dst[i] = one4;
}

// ============================================================================
// P2: c_attn[b][o] = attn_x[b] . W_comb[o][H:2H] + b_comb[o]  (once)
// ============================================================================
extern "C" __global__ void __launch_bounds__(256)
p2_kernel(const float* __restrict__ W_comb, const float* __restrict__ b_comb) {
    __shared__ float s_in[B][128];
    int tid = threadIdx.x;
    int ob = blockIdx.x * 32;
    int o = tid & 31, bq = tid >> 5;
    float acc[4] = {0.f, 0.f, 0.f, 0.f};
    const float* wrow = W_comb + (size_t)(ob + o) * (2 * H) + H;
    for (int kc = 0; kc < H; kc += 128) {
        for (int i = tid; i < B * 128; i += 256) {
            int b = i >> 7, k = i & 127;
            s_in[b][k] = g_attnx[b][kc + k];
        }
        __syncthreads();
        #pragma unroll 4
        for (int k = 0; k < 128; k += 4) {
            float4 w = *reinterpret_cast<const float4*>(wrow + kc + k);
            #pragma unroll
            for (int j = 0; j < 4; j++) {
                int b = bq + 8 * j;
                float4 xv = *reinterpret_cast<const float4*>(&s_in[b][k]);
                acc[j] += xv.x * w.x + xv.y * w.y + xv.z * w.z + xv.w * w.w;
            }
        }
        __syncthreads();
    }
    #pragma unroll
    for (int j = 0; j < 4; j++) {
        int b = bq + 8 * j;
        g_cattn[b][ob + o] = acc[j] + b_comb[ob + o];
    }
}

// ============================================================================
// K1: blocks 0..63  : (t>0: merge prev partials -> tok, logZ[t-1]) then
//                     xc = relu(emb[tok] @ Wcomb_x^T + c_attn)   (8 outs/blk)
//     blocks 64..255: gh = h @ W_hh^T + b_hh                      (8 outs/blk)
// One (b, o) pair per thread; 2 split accumulators (halved FFMA chain).
// ============================================================================
extern "C" __global__ void __launch_bounds__(256)
k1_kernel(int t, int cur, const float* __restrict__ emb, const int* __restrict__ y,
          const float* __restrict__ W_comb, const float* __restrict__ W_hh,
          const float* __restrict__ b_hh) {
    __shared__ float s_in[B][128];
    __shared__ int   s_tok[B];
    __shared__ float sm_m[8][B], sm_s[8][B], sm_av[8][B];
    __shared__ int   sm_ai[8][B];

    int tid = threadIdx.x;
    int bid = blockIdx.x;
    bool is_xc = (bid < 64);

    if (is_xc) {
        if (t > 0) {
            int b = tid & 31, part = tid >> 5;
            float m = -INFINITY, s = 0.f, av = -INFINITY;
            int ai = INT_MAX;
            for (int i = part; i < NPB; i += 8) {
                float pm = g_pmax[i][b];
                float ps = g_psum[i][b];
                int   pi = g_pidx[i][b];
                if (pm > m) { s = s * expf(m - pm) + ps; m = pm; }
                else        { s += ps * expf(pm - m); }
                if (pm > av || (pm == av && pi < ai)) { av = pm; ai = pi; }
            }
            sm_m[part][b] = m; sm_s[part][b] = s; sm_av[part][b] = av; sm_ai[part][b] = ai;
            __syncthreads();
            if (tid < B) {
                float M = -INFINITY, S = 0.f, AV = -INFINITY;
                int AI = INT_MAX;
                #pragma unroll
                for (int p = 0; p < 8; p++) {
                    float pm = sm_m[p][tid], ps = sm_s[p][tid];
                    if (pm > M) { S = S * expf(M - pm) + ps; M = pm; }
                    else        { S += ps * expf(pm - M); }
                    float v2 = sm_av[p][tid]; int i2 = sm_ai[p][tid];
                    if (v2 > AV || (v2 == AV && i2 < AI)) { AV = v2; AI = i2; }
                }
                s_tok[tid] = AI;
                if (bid == 0) g_logZ[t - 1][tid] = M + logf(S);
            }
        } else {
            if (tid < B) s_tok[tid] = y[tid * TOUT];  // y[b][0]
        }
        __syncthreads();
    }

    int o_l = tid & 7, b = tid >> 3;
    int o = is_xc ? (bid * 8 + o_l) : ((bid - 64) * 8 + o_l);
    const float* wrow = is_xc ? (W_comb + (size_t)o * (2 * H))
                              : (W_hh + (size_t)o * H);
    float a0 = 0.f, a1 = 0.f;
    for (int kc = 0; kc < H; kc += 128) {
        for (int i = tid; i < B * 128; i += 256) {
            int bb = i >> 7, k = i & 127;
            s_in[bb][k] = is_xc ? emb[(size_t)s_tok[bb] * H + kc + k]
                                : g_h[cur][bb][kc + k];
        }
        __syncthreads();
        #pragma unroll
        for (int k = 0; k < 128; k += 8) {
            float4 w0 = *reinterpret_cast<const float4*>(wrow + kc + k);
            float4 w1 = *reinterpret_cast<const float4*>(wrow + kc + k + 4);
            float4 x0 = *reinterpret_cast<const float4*>(&s_in[b][k]);
            float4 x1 = *reinterpret_cast<const float4*>(&s_in[b][k + 4]);
            a0 += w0.x * x0.x + w0.y * x0.y + w0.z * x0.z + w0.w * x0.w;
            a1 += w1.x * x1.x + w1.y * x1.y + w1.z * x1.z + w1.w * x1.w;
        }
        __syncthreads();
    }
    float r = a0 + a1;
    if (is_xc) {
        r += g_cattn[b][o];
        g_xc[b][o] = r > 0.f ? r : 0.f;
    } else {
        g_gh[b][o] = r + b_hh[o];
    }
}

// ============================================================================
// K2: gi = xc @ W_ih^T + b_ih ; fused GRU elementwise -> h_new
// grid 64, thread owns (b, o): 3 gates x 2 split accumulators.
// ============================================================================
extern "C" __global__ void __launch_bounds__(256)
k2_kernel(int t, int cur, const float* __restrict__ W_ih,
          const float* __restrict__ b_ih, float* __restrict__ d_out) {
    __shared__ float s_xc[B][128];
    int tid = threadIdx.x;
    int o_l = tid & 7, b = tid >> 3;
    int o = blockIdx.x * 8 + o_l;
    const float* w0 = W_ih + (size_t)o * H;
    const float* w1 = W_ih + (size_t)(o + H) * H;
    const float* w2 = W_ih + (size_t)(o + 2 * H) * H;
    float a0a = 0.f, a0b = 0.f, a1a = 0.f, a1b = 0.f, a2a = 0.f, a2b = 0.f;
    for (int kc = 0; kc < H; kc += 128) {
        for (int i = tid; i < B * 128; i += 256) {
            int bb = i >> 7, k = i & 127;
            s_xc[bb][k] = g_xc[bb][kc + k];
        }
        __syncthreads();
        #pragma unroll
        for (int k = 0; k < 128; k += 8) {
            float4 x0 = *reinterpret_cast<const float4*>(&s_xc[b][k]);
            float4 x1 = *reinterpret_cast<const float4*>(&s_xc[b][k + 4]);
            float4 u;
            u = *reinterpret_cast<const float4*>(w0 + kc + k);
            a0a += x0.x * u.x + x0.y * u.y + x0.z * u.z + x0.w * u.w;
            u = *reinterpret_cast<const float4*>(w0 + kc + k + 4);
            a0b += x1.x * u.x + x1.y * u.y + x1.z * u.z + x1.w * u.w;
            u = *reinterpret_cast<const float4*>(w1 + kc + k);
            a1a += x0.x * u.x + x0.y * u.y + x0.z * u.z + x0.w * u.w;
            u = *reinterpret_cast<const float4*>(w1 + kc + k + 4);
            a1b += x1.x * u.x + x1.y * u.y + x1.z * u.z + x1.w * u.w;
            u = *reinterpret_cast<const float4*>(w2 + kc + k);
            a2a += x0.x * u.x + x0.y * u.y + x0.z * u.z + x0.w * u.w;
            u = *reinterpret_cast<const float4*>(w2 + kc + k + 4);
            a2b += x1.x * u.x + x1.y * u.y + x1.z * u.z + x1.w * u.w;
        }
        __syncthreads();
    }
    float ir  = a0a + a0b + b_ih[o];
    float iz  = a1a + a1b + b_ih[o + H];
    float inn = a2a + a2b + b_ih[o + 2 * H];
    float ghr = g_gh[b][o];
    float ghz = g_gh[b][o + H];
    float ghn = g_gh[b][o + 2 * H];
    float r  = 1.f / (1.f + expf(-(ir + ghr)));
    float zz = 1.f / (1.f + expf(-(iz + ghz)));
    float n  = tanhf(inn + r * ghn);
    float hp = g_h[cur][b][o];
    float hn = (1.f - zz) * n + zz * hp;
    g_h[cur ^ 1][b][o] = hn;
    if (t == TOUT - 1) d_out[OFF_HT + (size_t)b * H + o] = hn;
}

// ============================================================================
// KC: z = h_new @ W_out^T + b_out   (f32x2, 8b x 4v per thread,
//     cp.async double-buffered W tiles, h broadcast from smem)
//     writes raw z to zbuf[t][b][v] + per-block (max, argmax, sumexp) partials
// ============================================================================
__device__ __forceinline__ void kc_issue(int buf, int kc, int tid, int vbase,
                                         const float* __restrict__ W_out,
                                         const float* __restrict__ hptr,
                                         ulonglong2 (*wsm)[8][128],
                                         ulonglong2 (*hsm)[B][8]) {
    #pragma unroll
    for (int p = 0; p < 8; p++) {
        int idx = p * 128 + tid;
        int vl = idx & 127, kq = idx >> 7;
        cpa16(sm_u32(&wsm[buf][kq][vl]),
              W_out + (size_t)(vbase + vl) * H + kc + 4 * kq);
    }
    #pragma unroll
    for (int p = 0; p < 2; p++) {
        int idx = p * 128 + tid;
        int bb = idx >> 3, kq = idx & 7;
        cpa16(sm_u32(&hsm[buf][bb][kq]),
              hptr + (size_t)bb * H + kc + 4 * kq);
    }
    asm volatile("cp.async.commit_group;");
}

extern "C" __global__ void __launch_bounds__(128)
kc_kernel(int t, int hidx, const float* __restrict__ W_out,
          const float* __restrict__ b_out) {
    __shared__ ulonglong2 wsm[2][8][128];   // [buf][kq][v]  32 KB
    __shared__ ulonglong2 hsm[2][B][8];     // [buf][b][kq]   8 KB
    int tid = threadIdx.x;
    int vg = tid & 31, bg = tid >> 5;       // bg in 0..3 (warp id)
    int vbase = blockIdx.x * VPB;
    const float* hptr = &g_h[hidx][0][0];

    unsigned long long acc[8][4];
    #pragma unroll
    for (int j = 0; j < 8; j++)
        #pragma unroll
        for (int i = 0; i < 4; i++) acc[j][i] = 0ull;

    kc_issue(0, 0, tid, vbase, W_out, hptr, wsm, hsm);

    for (int c = 0; c < 16; c++) {
        int buf = c & 1;
        if (c < 15) {
            kc_issue(buf ^ 1, (c + 1) * 32, tid, vbase, W_out, hptr, wsm, hsm);
            asm volatile("cp.async.wait_group 1;");
        } else {
            asm volatile("cp.async.wait_group 0;");
        }
        __syncthreads();
        #pragma unroll
        for (int kq = 0; kq < 8; kq++) {
            ulonglong2 hv[8];
            #pragma unroll
            for (int j = 0; j < 8; j++) hv[j] = hsm[buf][bg + 4 * j][kq];  // broadcast
            #pragma unroll
            for (int i = 0; i < 4; i++) {
                ulonglong2 wv = wsm[buf][kq][vg + 32 * i];
                #pragma unroll
                for (int j = 0; j < 8; j++) {
                    acc[j][i] = fma2(hv[j].x, wv.x, acc[j][i]);
                    acc[j][i] = fma2(hv[j].y, wv.y, acc[j][i]);
                }
            }
        }
        __syncthreads();
    }

    float bo[4];
    #pragma unroll
    for (int i = 0; i < 4; i++) bo[i] = b_out[vbase + vg + 32 * i];

    #pragma unroll
    for (int j = 0; j < 8; j++) {
        int b = bg + 4 * j;
        float zv[4];
        float lmax = -INFINITY;
        int lidx = 0;
        #pragma unroll
        for (int i = 0; i < 4; i++) {
            float lo, hi;
            upk(acc[j][i], lo, hi);
            int v = vbase + vg + 32 * i;
            float z = lo + hi + bo[i];
            zv[i] = z;
            g_zbuf[((size_t)t * B + b) * V + v] = z;
            if (z > lmax) { lmax = z; lidx = v; }  // first occurrence (v ascending)
        }
        float wm = lmax;
        int wi = lidx;
        #pragma unroll
        for (int off = 16; off; off >>= 1) {
            float om = __shfl_xor_sync(0xffffffffu, wm, off);
            int   oi = __shfl_xor_sync(0xffffffffu, wi, off);
            if (om > wm || (om == wm && oi < wi)) { wm = om; wi = oi; }
        }
        float ls = 0.f;
        #pragma unroll
        for (int i = 0; i < 4; i++) ls += expf(zv[i] - wm);
        #pragma unroll
        for (int off = 16; off; off >>= 1)
            ls += __shfl_xor_sync(0xffffffffu, ls, off);
        if (vg == 0) {
            g_pmax[blockIdx.x][b] = wm;
            g_psum[blockIdx.x][b] = ls;
            g_pidx[blockIdx.x][b] = wi;
        }
    }
}

// ============================================================================
// E1: final logZ for t = TOUT-1
// ============================================================================
extern "C" __global__ void __launch_bounds__(256) e1_kernel() {
    __shared__ float sm_m[8][B], sm_s[8][B];
    int tid = threadIdx.x;
    int b = tid & 31, part = tid >> 5;
    float m = -INFINITY, s = 0.f;
    for (int i = part; i < NPB; i += 8) {
        float pm = g_pmax[i][b], ps = g_psum[i][b];
        if (pm > m) { s = s * expf(m - pm) + ps; m = pm; }
        else        { s += ps * expf(pm - m); }
    }
    sm_m[part][b] = m; sm_s[part][b] = s;
    __syncthreads();
    if (tid < B) {
        float M = -INFINITY, S = 0.f;
        #pragma unroll
        for (int p = 0; p < 8; p++) {
            float pm = sm_m[p][tid], ps = sm_s[p][tid];
            if (pm > M) { S = S * expf(M - pm) + ps; M = pm; }
            else        { S += ps * expf(pm - M); }
        }
        g_logZ[TOUT - 1][tid] = M + logf(S);
    }
}

// ============================================================================
// E2: out[b][v][t] = z[t][b][v] - logZ[t][b]   (smem-tiled transpose)
// ============================================================================
extern "C" __global__ void __launch_bounds__(256)
e2_kernel(float* __restrict__ d_out) {
    __shared__ float s_z[128][52];
    __shared__ float s_lz[TOUT];
    int b = blockIdx.y;
    int v0 = blockIdx.x * 128;
    int tid = threadIdx.x;
    if (tid < TOUT) s_lz[tid] = g_logZ[tid][b];
    __syncthreads();
    for (int j = tid; j < 128 * TOUT; j += 256) {
        int tt = j >> 7, vl = j & 127;
        s_z[vl][tt] = g_zbuf[((size_t)tt * B + b) * V + v0 + vl] - s_lz[tt];
    }
    __syncthreads();
    size_t base = ((size_t)b * V + v0) * TOUT;
    for (int j = tid; j < 128 * TOUT; j += 256) {
        int vl = j / TOUT, tt = j % TOUT;
        d_out[base + j] = s_z[vl][tt];
    }
}

// ============================================================================
extern "C" void kernel_launch(void* const* d_in, const int* in_sizes, int n_in,
                              void* d_out_v, int out_size) {
    const float* enc    = (const float*)d_in[0];
    const int*   y      = (const int*)d_in[1];
    const float* emb    = (const float*)d_in[2];
    // d_in[3..6]: W_fc, b_fc, W_fc1, W_fc2 — dead (softmax over singleton axis)
    const float* W_comb = (const float*)d_in[7];
    const float* b_comb = (const float*)d_in[8];
    const float* W_ih   = (const float*)d_in[9];
    const float* W_hh   = (const float*)d_in[10];
    const float* b_ih   = (const float*)d_in[11];
    const float* b_hh   = (const float*)d_in[12];
    const float* W_out  = (const float*)d_in[13];
    const float* b_out  = (const float*)d_in[14];
    float* d_out = (float*)d_out_v;

    p1_kernel<<<512, 256>>>(enc, d_out);
    p2_kernel<<<16, 256>>>(W_comb, b_comb);
    for (int t = 0; t < TOUT; t++) {
        int cur = t & 1;
        k1_kernel<<<256, 256>>>(t, cur, emb, y, W_comb, W_hh, b_hh);
        k2_kernel<<<64, 256>>>(t, cur, W_ih, b_ih, d_out);
        kc_kernel<<<NPB, 128>>>(t, cur ^ 1, W_out, b_out);
    }
    e1_kernel<<<1, 256>>>();
    e2_kernel<<<dim3(V / 128, B), 256>>>(d_out);
}

// round 3
// speedup vs baseline: 1.8629x; 1.2596x over previous
#include <cuda_runtime.h>
#include <math.h>
#include <stdint.h>
#include <limits.h>

#define B    32
#define H    512
#define V    32000
#define TIN  50
#define TOUT 50
#define NPB  250      // projection blocks (V / VPB)
#define VPB  128      // v-columns per projection block

#define OFF_HT   ((size_t)B * V * TOUT)          // 51,200,000
#define OFF_ATTN (OFF_HT + (size_t)B * H)        // 51,216,384

// ---------------- device scratch (static, allowed) ----------------
__device__ float g_zbuf[(size_t)TOUT * B * V];   // raw logits, 204.8 MB
__device__ float g_pmax[NPB][B];
__device__ float g_psum[NPB][B];
__device__ int   g_pidx[NPB][B];
__device__ float g_logZ[TOUT][B];
__device__ float g_h[2][B][H];
__device__ float g_xc[B][H];
__device__ float g_gh[B][3 * H];
__device__ float g_attnx[B][H];
__device__ float g_cattn[B][H];
__device__ int   g_tok[B];
__device__ unsigned g_cnt;

// ---------------- helpers ----------------
__device__ __forceinline__ unsigned long long fma2(unsigned long long a,
                                                   unsigned long long b,
                                                   unsigned long long c) {
    unsigned long long d;
    asm("fma.rn.f32x2 %0, %1, %2, %3;" : "=l"(d) : "l"(a), "l"(b), "l"(c));
    return d;
}
__device__ __forceinline__ void upk(unsigned long long v, float& lo, float& hi) {
    asm("mov.b64 {%0, %1}, %2;" : "=f"(lo), "=f"(hi) : "l"(v));
}
__device__ __forceinline__ unsigned sm_u32(const void* p) {
    return (unsigned)__cvta_generic_to_shared(p);
}
__device__ __forceinline__ void cpa16(unsigned d, const void* s) {
    asm volatile("cp.async.cg.shared.global [%0], [%1], 16;" :: "r"(d), "l"(s));
}

// ============================================================================
// P1: attn_x = sum_t encoder_out ; h0 = 0 ; attn output = ones ; tok0 ; cnt=0
// ============================================================================
extern "C" __global__ void p1_kernel(const float* __restrict__ enc,
                                     const int* __restrict__ y,
                                     float* __restrict__ d_out) {
    int gid  = blockIdx.x * blockDim.x + threadIdx.x;
    int nthr = gridDim.x * blockDim.x;
    if (gid < B) g_tok[gid] = y[gid * TOUT];     // y[b][0]
    if (gid == 0) g_cnt = 0u;
    for (int i = gid; i < B * H; i += nthr) {
        int b = i >> 9, k = i & 511;
        g_h[0][b][k] = 0.f;
        float s = 0.f;
        #pragma unroll 5
        for (int tt = 0; tt < TIN; tt++) s += enc[((size_t)b * TIN + tt) * H + k];
        g_attnx[b][k] = s;
    }
    float4 one4 = make_float4(1.f, 1.f, 1.f, 1.f);
    float4* dst = reinterpret_cast<float4*>(d_out + OFF_ATTN);
    size_t n4 = (size_t)TOUT * B * TIN * H / 4;
    for (size_t i = gid; i < n4; i += nthr) dst[i] = one4;
}

// ============================================================================
// P2: c_attn[b][o] = attn_x[b] . W_comb[o][H:2H] + b_comb[o]  (once)
// lane = b, warp covers o; uniform W loads; transposed smem.
// ============================================================================
extern "C" __global__ void __launch_bounds__(256)
p2_kernel(const float* __restrict__ W_comb, const float* __restrict__ b_comb) {
    __shared__ float hs[128][33];
    int tid = threadIdx.x;
    int lane = tid & 31, w = tid >> 5;
    int o0 = blockIdx.x * 16 + w * 2;                  // grid 32
    const float* r0 = W_comb + (size_t)o0 * (2 * H) + H;
    const float* r1 = W_comb + (size_t)(o0 + 1) * (2 * H) + H;
    float a0 = 0.f, a1 = 0.f;
    for (int kc = 0; kc < H; kc += 128) {
        for (int i = tid; i < B * 128; i += 256) {
            int b = i >> 7, k = i & 127;
            hs[k][b] = g_attnx[b][kc + k];
        }
        __syncthreads();
        #pragma unroll 8
        for (int k = 0; k < 128; k += 4) {
            float4 u0 = *reinterpret_cast<const float4*>(r0 + kc + k);
            float4 u1 = *reinterpret_cast<const float4*>(r1 + kc + k);
            float x0 = hs[k][lane], x1 = hs[k + 1][lane];
            float x2 = hs[k + 2][lane], x3 = hs[k + 3][lane];
            a0 += u0.x * x0 + u0.y * x1 + u0.z * x2 + u0.w * x3;
            a1 += u1.x * x0 + u1.y * x1 + u1.z * x2 + u1.w * x3;
        }
        __syncthreads();
    }
    g_cattn[lane][o0]     = a0 + b_comb[o0];
    g_cattn[lane][o0 + 1] = a1 + b_comb[o0 + 1];
}

// ============================================================================
// K1: blocks 0..31  : xc = relu(emb[tok] @ Wcomb_x^T + c_attn)  (16 rows/blk)
//     blocks 32..127: gh = h @ W_hh^T + b_hh                    (16 rows/blk)
// lane = b; each thread 2 rows; W loads warp-uniform; hs transposed (no conflicts)
// ============================================================================
extern "C" __global__ void __launch_bounds__(256)
k1_kernel(int cur, const float* __restrict__ emb,
          const float* __restrict__ W_comb, const float* __restrict__ W_hh,
          const float* __restrict__ b_hh) {
    __shared__ float hs[128][33];
    __shared__ int s_tok[B];
    int tid = threadIdx.x, bid = blockIdx.x;
    int lane = tid & 31, w = tid >> 5;
    bool is_xc = (bid < 32);
    int o0 = is_xc ? (bid * 16 + w * 2) : ((bid - 32) * 16 + w * 2);
    const float* r0 = is_xc ? (W_comb + (size_t)o0 * (2 * H))
                            : (W_hh + (size_t)o0 * H);
    const float* r1 = is_xc ? (W_comb + (size_t)(o0 + 1) * (2 * H))
                            : (W_hh + (size_t)(o0 + 1) * H);
    if (is_xc && tid < B) s_tok[tid] = g_tok[tid];
    __syncthreads();

    float a0a = 0.f, a0b = 0.f, a1a = 0.f, a1b = 0.f;
    for (int kc = 0; kc < H; kc += 128) {
        for (int i = tid; i < B * 128; i += 256) {
            int b = i >> 7, k = i & 127;
            hs[k][b] = is_xc ? emb[(size_t)s_tok[b] * H + kc + k]
                             : g_h[cur][b][kc + k];
        }
        __syncthreads();
        #pragma unroll 8
        for (int k = 0; k < 128; k += 4) {
            float4 u0 = *reinterpret_cast<const float4*>(r0 + kc + k);
            float4 u1 = *reinterpret_cast<const float4*>(r1 + kc + k);
            float x0 = hs[k][lane], x1 = hs[k + 1][lane];
            float x2 = hs[k + 2][lane], x3 = hs[k + 3][lane];
            a0a += u0.x * x0 + u0.y * x1;  a0b += u0.z * x2 + u0.w * x3;
            a1a += u1.x * x0 + u1.y * x1;  a1b += u1.z * x2 + u1.w * x3;
        }
        __syncthreads();
    }
    float v0 = a0a + a0b, v1 = a1a + a1b;
    if (is_xc) {
        v0 += g_cattn[lane][o0];
        v1 += g_cattn[lane][o0 + 1];
        g_xc[lane][o0]     = v0 > 0.f ? v0 : 0.f;
        g_xc[lane][o0 + 1] = v1 > 0.f ? v1 : 0.f;
    } else {
        g_gh[lane][o0]     = v0 + b_hh[o0];
        g_gh[lane][o0 + 1] = v1 + b_hh[o0 + 1];
    }
}

// ============================================================================
// K2: gi = xc @ W_ih^T + b_ih ; fused GRU -> h_new
// grid 128, block = 4 o; 8 warps = (o_l in 0..3) x (k-half in 0..1);
// lane = b; smem reduce of k-halves; GRU by first 128 threads.
// ============================================================================
extern "C" __global__ void __launch_bounds__(256)
k2_kernel(int t, int cur, const float* __restrict__ W_ih,
          const float* __restrict__ b_ih, float* __restrict__ d_out) {
    __shared__ float hs[128][33];
    __shared__ float sp[3][8][33];
    int tid = threadIdx.x;
    int lane = tid & 31, w = tid >> 5;
    int o_l = w & 3, half = w >> 2;
    int o = blockIdx.x * 4 + o_l;
    const float* wr = W_ih + (size_t)o * H;
    const float* wz = W_ih + (size_t)(o + H) * H;
    const float* wn = W_ih + (size_t)(o + 2 * H) * H;
    float ar = 0.f, az = 0.f, an = 0.f;
    for (int c = 0; c < 4; c++) {
        int kc = c * 128;
        for (int i = tid; i < B * 128; i += 256) {
            int b = i >> 7, k = i & 127;
            hs[k][b] = g_xc[b][kc + k];
        }
        __syncthreads();
        if ((c >> 1) == half) {
            #pragma unroll 8
            for (int k = 0; k < 128; k += 4) {
                float x0 = hs[k][lane], x1 = hs[k + 1][lane];
                float x2 = hs[k + 2][lane], x3 = hs[k + 3][lane];
                float4 u;
                u = *reinterpret_cast<const float4*>(wr + kc + k);
                ar += u.x * x0 + u.y * x1 + u.z * x2 + u.w * x3;
                u = *reinterpret_cast<const float4*>(wz + kc + k);
                az += u.x * x0 + u.y * x1 + u.z * x2 + u.w * x3;
                u = *reinterpret_cast<const float4*>(wn + kc + k);
                an += u.x * x0 + u.y * x1 + u.z * x2 + u.w * x3;
            }
        }
        __syncthreads();
    }
    sp[0][w][lane] = ar;
    sp[1][w][lane] = az;
    sp[2][w][lane] = an;
    __syncthreads();
    if (tid < 128) {
        int b = tid & 31, ol = tid >> 5;
        int oo = blockIdx.x * 4 + ol;
        float ir  = sp[0][ol][b] + sp[0][ol + 4][b] + b_ih[oo];
        float iz  = sp[1][ol][b] + sp[1][ol + 4][b] + b_ih[oo + H];
        float inn = sp[2][ol][b] + sp[2][ol + 4][b] + b_ih[oo + 2 * H];
        float r  = 1.f / (1.f + expf(-(ir + g_gh[b][oo])));
        float zz = 1.f / (1.f + expf(-(iz + g_gh[b][oo + H])));
        float n  = tanhf(inn + r * g_gh[b][oo + 2 * H]);
        float hp = g_h[cur][b][oo];
        float hn = (1.f - zz) * n + zz * hp;
        g_h[cur ^ 1][b][oo] = hn;
        if (t == TOUT - 1) d_out[OFF_HT + (size_t)b * H + oo] = hn;
    }
}

// ============================================================================
// KC: z = h_new @ W_out^T + b_out (f32x2, cp.async double-buffered)
//     + per-block (max, argmax, sumexp) partials
//     + LAST-BLOCK epilogue: merge partials -> g_tok (next step), g_logZ[t]
// ============================================================================
__device__ __forceinline__ void kc_issue(int buf, int kc, int tid, int vbase,
                                         const float* __restrict__ W_out,
                                         const float* __restrict__ hptr,
                                         ulonglong2 (*wsm)[8][128],
                                         ulonglong2 (*hsm)[B][8]) {
    #pragma unroll
    for (int p = 0; p < 8; p++) {
        int idx = p * 128 + tid;
        int vl = idx & 127, kq = idx >> 7;
        cpa16(sm_u32(&wsm[buf][kq][vl]),
              W_out + (size_t)(vbase + vl) * H + kc + 4 * kq);
    }
    #pragma unroll
    for (int p = 0; p < 2; p++) {
        int idx = p * 128 + tid;
        int bb = idx >> 3, kq = idx & 7;
        cpa16(sm_u32(&hsm[buf][bb][kq]),
              hptr + (size_t)bb * H + kc + 4 * kq);
    }
    asm volatile("cp.async.commit_group;");
}

extern "C" __global__ void __launch_bounds__(128)
kc_kernel(int t, int hidx, const float* __restrict__ W_out,
          const float* __restrict__ b_out) {
    __shared__ ulonglong2 wsm[2][8][128];   // 32 KB
    __shared__ ulonglong2 hsm[2][B][8];     //  8 KB
    __shared__ unsigned s_last;
    __shared__ float sm_m[4][B], sm_s[4][B], sm_av[4][B];
    __shared__ int   sm_ai[4][B];

    int tid = threadIdx.x;
    int vg = tid & 31, bg = tid >> 5;       // bg = warp id (0..3)
    int vbase = blockIdx.x * VPB;
    const float* hptr = &g_h[hidx][0][0];

    unsigned long long acc[8][4];
    #pragma unroll
    for (int j = 0; j < 8; j++)
        #pragma unroll
        for (int i = 0; i < 4; i++) acc[j][i] = 0ull;

    kc_issue(0, 0, tid, vbase, W_out, hptr, wsm, hsm);

    for (int c = 0; c < 16; c++) {
        int buf = c & 1;
        if (c < 15) {
            kc_issue(buf ^ 1, (c + 1) * 32, tid, vbase, W_out, hptr, wsm, hsm);
            asm volatile("cp.async.wait_group 1;");
        } else {
            asm volatile("cp.async.wait_group 0;");
        }
        __syncthreads();
        #pragma unroll
        for (int kq = 0; kq < 8; kq++) {
            ulonglong2 hv[8];
            #pragma unroll
            for (int j = 0; j < 8; j++) hv[j] = hsm[buf][bg + 4 * j][kq];  // bcast
            #pragma unroll
            for (int i = 0; i < 4; i++) {
                ulonglong2 wv = wsm[buf][kq][vg + 32 * i];
                #pragma unroll
                for (int j = 0; j < 8; j++) {
                    acc[j][i] = fma2(hv[j].x, wv.x, acc[j][i]);
                    acc[j][i] = fma2(hv[j].y, wv.y, acc[j][i]);
                }
            }
        }
        __syncthreads();
    }

    float bo[4];
    #pragma unroll
    for (int i = 0; i < 4; i++) bo[i] = b_out[vbase + vg + 32 * i];

    #pragma unroll
    for (int j = 0; j < 8; j++) {
        int b = bg + 4 * j;
        float zv[4];
        float lmax = -INFINITY;
        int lidx = 0;
        #pragma unroll
        for (int i = 0; i < 4; i++) {
            float lo, hi;
            upk(acc[j][i], lo, hi);
            int v = vbase + vg + 32 * i;
            float z = lo + hi + bo[i];
            zv[i] = z;
            g_zbuf[((size_t)t * B + b) * V + v] = z;
            if (z > lmax) { lmax = z; lidx = v; }  // first occurrence (v ascending)
        }
        float wm = lmax;
        int wi = lidx;
        #pragma unroll
        for (int off = 16; off; off >>= 1) {
            float om = __shfl_xor_sync(0xffffffffu, wm, off);
            int   oi = __shfl_xor_sync(0xffffffffu, wi, off);
            if (om > wm || (om == wm && oi < wi)) { wm = om; wi = oi; }
        }
        float ls = 0.f;
        #pragma unroll
        for (int i = 0; i < 4; i++) ls += expf(zv[i] - wm);
        #pragma unroll
        for (int off = 16; off; off >>= 1)
            ls += __shfl_xor_sync(0xffffffffu, ls, off);
        if (vg == 0) {
            g_pmax[blockIdx.x][b] = wm;
            g_psum[blockIdx.x][b] = ls;
            g_pidx[blockIdx.x][b] = wi;
        }
    }

    // ---- last-block merge: tok for next step + logZ[t] ----
    __threadfence();
    __syncthreads();
    if (tid == 0) s_last = atomicAdd(&g_cnt, 1u);
    __syncthreads();
    if (s_last == NPB - 1) {
        __threadfence();
        int b = tid & 31, part = tid >> 5;   // 4 parts
        float m = -INFINITY, s = 0.f, av = -INFINITY;
        int ai = INT_MAX;
        for (int i = part; i < NPB; i += 4) {
            float pm = g_pmax[i][b];
            float ps = g_psum[i][b];
            int   pi = g_pidx[i][b];
            if (pm > m) { s = s * expf(m - pm) + ps; m = pm; }
            else        { s += ps * expf(pm - m); }
            if (pm > av || (pm == av && pi < ai)) { av = pm; ai = pi; }
        }
        sm_m[part][b] = m; sm_s[part][b] = s; sm_av[part][b] = av; sm_ai[part][b] = ai;
        __syncthreads();
        if (tid < B) {
            float M = -INFINITY, S = 0.f, AV = -INFINITY;
            int AI = INT_MAX;
            #pragma unroll
            for (int p = 0; p < 4; p++) {
                float pm = sm_m[p][tid], ps = sm_s[p][tid];
                if (pm > M) { S = S * expf(M - pm) + ps; M = pm; }
                else        { S += ps * expf(pm - M); }
                float v2 = sm_av[p][tid]; int i2 = sm_ai[p][tid];
                if (v2 > AV || (v2 == AV && i2 < AI)) { AV = v2; AI = i2; }
            }
            g_tok[tid] = AI;
            g_logZ[t][tid] = M + logf(S);
        }
        if (tid == 0) g_cnt = 0u;
    }
}

// ============================================================================
// E2: out[b][v][t] = z[t][b][v] - logZ[t][b]   (smem-tiled transpose)
// ============================================================================
extern "C" __global__ void __launch_bounds__(256)
e2_kernel(float* __restrict__ d_out) {
    __shared__ float s_z[128][52];
    __shared__ float s_lz[TOUT];
    int b = blockIdx.y;
    int v0 = blockIdx.x * 128;
    int tid = threadIdx.x;
    if (tid < TOUT) s_lz[tid] = g_logZ[tid][b];
    __syncthreads();
    for (int j = tid; j < 128 * TOUT; j += 256) {
        int tt = j >> 7, vl = j & 127;
        s_z[vl][tt] = g_zbuf[((size_t)tt * B + b) * V + v0 + vl] - s_lz[tt];
    }
    __syncthreads();
    size_t base = ((size_t)b * V + v0) * TOUT;
    for (int j = tid; j < 128 * TOUT; j += 256) {
        int vl = j / TOUT, tt = j % TOUT;
        d_out[base + j] = s_z[vl][tt];
    }
}

// ============================================================================
extern "C" void kernel_launch(void* const* d_in, const int* in_sizes, int n_in,
                              void* d_out_v, int out_size) {
    const float* enc    = (const float*)d_in[0];
    const int*   y      = (const int*)d_in[1];
    const float* emb    = (const float*)d_in[2];
    // d_in[3..6]: W_fc, b_fc, W_fc1, W_fc2 — dead (softmax over singleton axis)
    const float* W_comb = (const float*)d_in[7];
    const float* b_comb = (const float*)d_in[8];
    const float* W_ih   = (const float*)d_in[9];
    const float* W_hh   = (const float*)d_in[10];
    const float* b_ih   = (const float*)d_in[11];
    const float* b_hh   = (const float*)d_in[12];
    const float* W_out  = (const float*)d_in[13];
    const float* b_out  = (const float*)d_in[14];
    float* d_out = (float*)d_out_v;

    p1_kernel<<<512, 256>>>(enc, y, d_out);
    p2_kernel<<<32, 256>>>(W_comb, b_comb);
    for (int t = 0; t < TOUT; t++) {
        int cur = t & 1;
        k1_kernel<<<128, 256>>>(cur, emb, W_comb, W_hh, b_hh);
        k2_kernel<<<128, 256>>>(t, cur, W_ih, b_ih, d_out);
        kc_kernel<<<NPB, 128>>>(t, cur ^ 1, W_out, b_out);
    }
    e2_kernel<<<dim3(V / 128, B), 256>>>(d_out);
}

// round 4
// speedup vs baseline: 2.3073x; 1.2385x over previous
#include <cuda_runtime.h>
#include <math.h>
#include <stdint.h>
#include <limits.h>

#define B    32
#define H    512
#define V    32000
#define TIN  50
#define TOUT 50
#define NPB  125      // projection blocks (V / VPB) -- single wave on 148 SMs
#define VPB  256      // v-columns per projection block

#define OFF_HT   ((size_t)B * V * TOUT)          // 51,200,000
#define OFF_ATTN (OFF_HT + (size_t)B * H)        // 51,216,384

// ---------------- device scratch (static, allowed) ----------------
__device__ float g_zbuf[(size_t)TOUT * B * V];   // raw logits, 204.8 MB
__device__ float g_pmax[NPB][B];
__device__ float g_psum[NPB][B];
__device__ int   g_pidx[NPB][B];
__device__ float g_logZ[TOUT][B];
__device__ float g_h[2][B][H];
__device__ float g_xc[B][H];
__device__ float g_gh[B][3 * H];
__device__ float g_attnx[B][H];
__device__ float g_cattn[B][H];
__device__ int   g_tok[B];
__device__ unsigned g_cnt;

// ---------------- helpers ----------------
__device__ __forceinline__ unsigned long long fma2(unsigned long long a,
                                                   unsigned long long b,
                                                   unsigned long long c) {
    unsigned long long d;
    asm("fma.rn.f32x2 %0, %1, %2, %3;" : "=l"(d) : "l"(a), "l"(b), "l"(c));
    return d;
}
__device__ __forceinline__ void upk(unsigned long long v, float& lo, float& hi) {
    asm("mov.b64 {%0, %1}, %2;" : "=f"(lo), "=f"(hi) : "l"(v));
}
__device__ __forceinline__ unsigned sm_u32(const void* p) {
    return (unsigned)__cvta_generic_to_shared(p);
}
__device__ __forceinline__ void cpa16(unsigned d, const void* s) {
    asm volatile("cp.async.cg.shared.global [%0], [%1], 16;" :: "r"(d), "l"(s));
}

// ============================================================================
// P1: attn_x = sum_t encoder_out ; h0 = 0 ; attn output = ones ; tok0 ; cnt=0
// ============================================================================
extern "C" __global__ void p1_kernel(const float* __restrict__ enc,
                                     const int* __restrict__ y,
                                     float* __restrict__ d_out) {
    int gid  = blockIdx.x * blockDim.x + threadIdx.x;
    int nthr = gridDim.x * blockDim.x;
    if (gid < B) g_tok[gid] = y[gid * TOUT];     // y[b][0]
    if (gid == 0) g_cnt = 0u;
    for (int i = gid; i < B * H; i += nthr) {
        int b = i >> 9, k = i & 511;
        g_h[0][b][k] = 0.f;
        float s = 0.f;
        #pragma unroll 5
        for (int tt = 0; tt < TIN; tt++) s += enc[((size_t)b * TIN + tt) * H + k];
        g_attnx[b][k] = s;
    }
    float4 one4 = make_float4(1.f, 1.f, 1.f, 1.f);
    float4* dst = reinterpret_cast<float4*>(d_out + OFF_ATTN);
    size_t n4 = (size_t)TOUT * B * TIN * H / 4;
    for (size_t i = gid; i < n4; i += nthr) dst[i] = one4;
}

// ============================================================================
// P2: c_attn[b][o] = attn_x[b] . W_comb[o][H:2H] + b_comb[o]  (once)
// ============================================================================
extern "C" __global__ void __launch_bounds__(256)
p2_kernel(const float* __restrict__ W_comb, const float* __restrict__ b_comb) {
    __shared__ float hs[128][33];
    int tid = threadIdx.x;
    int lane = tid & 31, w = tid >> 5;
    int o0 = blockIdx.x * 16 + w * 2;                  // grid 32
    const float* r0 = W_comb + (size_t)o0 * (2 * H) + H;
    const float* r1 = W_comb + (size_t)(o0 + 1) * (2 * H) + H;
    float a0 = 0.f, a1 = 0.f;
    for (int kc = 0; kc < H; kc += 128) {
        for (int i = tid; i < B * 128; i += 256) {
            int b = i >> 7, k = i & 127;
            hs[k][b] = g_attnx[b][kc + k];
        }
        __syncthreads();
        #pragma unroll 8
        for (int k = 0; k < 128; k += 4) {
            float4 u0 = *reinterpret_cast<const float4*>(r0 + kc + k);
            float4 u1 = *reinterpret_cast<const float4*>(r1 + kc + k);
            float x0 = hs[k][lane], x1 = hs[k + 1][lane];
            float x2 = hs[k + 2][lane], x3 = hs[k + 3][lane];
            a0 += u0.x * x0 + u0.y * x1 + u0.z * x2 + u0.w * x3;
            a1 += u1.x * x0 + u1.y * x1 + u1.z * x2 + u1.w * x3;
        }
        __syncthreads();
    }
    g_cattn[lane][o0]     = a0 + b_comb[o0];
    g_cattn[lane][o0 + 1] = a1 + b_comb[o0 + 1];
}

// ============================================================================
// K1: blocks 0..31  : xc = relu(emb[tok] @ Wcomb_x^T + c_attn)  (16 rows/blk)
//     blocks 32..127: gh = h @ W_hh^T + b_hh                    (16 rows/blk)
// Full-H smem staging (one sync), thread streams 2 W rows with huge MLP.
// ============================================================================
#define HS(k, b) hs[(k) * 33 + (b)]
extern "C" __global__ void __launch_bounds__(256)
k1_kernel(int cur, const float* __restrict__ emb,
          const float* __restrict__ W_comb, const float* __restrict__ W_hh,
          const float* __restrict__ b_hh) {
    extern __shared__ float hs[];        // [512][33] = 67584 B
    __shared__ int s_tok[B];
    int tid = threadIdx.x, bid = blockIdx.x;
    int lane = tid & 31, w = tid >> 5;
    bool is_xc = (bid < 32);
    int o0 = (is_xc ? bid * 16 : (bid - 32) * 16) + w * 2;
    const float* r0 = is_xc ? (W_comb + (size_t)o0 * (2 * H))
                            : (W_hh + (size_t)o0 * H);
    const float* r1 = is_xc ? (W_comb + (size_t)(o0 + 1) * (2 * H))
                            : (W_hh + (size_t)(o0 + 1) * H);
    if (is_xc && tid < B) s_tok[tid] = g_tok[tid];
    __syncthreads();

    for (int i = tid; i < B * H; i += 256) {
        int b = i >> 9, k = i & 511;
        HS(k, b) = is_xc ? emb[(size_t)s_tok[b] * H + k] : g_h[cur][b][k];
    }
    __syncthreads();

    float a0a = 0.f, a0b = 0.f, a1a = 0.f, a1b = 0.f;
    #pragma unroll 8
    for (int k = 0; k < H; k += 4) {
        float4 u0 = *reinterpret_cast<const float4*>(r0 + k);
        float4 u1 = *reinterpret_cast<const float4*>(r1 + k);
        float x0 = HS(k, lane), x1 = HS(k + 1, lane);
        float x2 = HS(k + 2, lane), x3 = HS(k + 3, lane);
        a0a += u0.x * x0 + u0.y * x1;  a0b += u0.z * x2 + u0.w * x3;
        a1a += u1.x * x0 + u1.y * x1;  a1b += u1.z * x2 + u1.w * x3;
    }
    float v0 = a0a + a0b, v1 = a1a + a1b;
    if (is_xc) {
        v0 += g_cattn[lane][o0];
        v1 += g_cattn[lane][o0 + 1];
        g_xc[lane][o0]     = v0 > 0.f ? v0 : 0.f;
        g_xc[lane][o0 + 1] = v1 > 0.f ? v1 : 0.f;
    } else {
        g_gh[lane][o0]     = v0 + b_hh[o0];
        g_gh[lane][o0 + 1] = v1 + b_hh[o0 + 1];
    }
}

// ============================================================================
// K2: gi = xc @ W_ih^T + b_ih ; fused GRU -> h_new
// Full-H staging; grid 128; warp = (o_l 0..3, k-half); smem reduce + GRU.
// ============================================================================
#define SP(g, ww, l) sp[((g) * 8 + (ww)) * 33 + (l)]
extern "C" __global__ void __launch_bounds__(256)
k2_kernel(int t, int cur, const float* __restrict__ W_ih,
          const float* __restrict__ b_ih, float* __restrict__ d_out) {
    extern __shared__ float smemf[];     // hs[512*33] + sp[3*8*33]
    float* hs = smemf;
    float* sp = smemf + 512 * 33;
    int tid = threadIdx.x;
    int lane = tid & 31, w = tid >> 5;
    int o_l = w & 3, half = w >> 2;
    int o = blockIdx.x * 4 + o_l;
    const float* wr = W_ih + (size_t)o * H;
    const float* wz = W_ih + (size_t)(o + H) * H;
    const float* wn = W_ih + (size_t)(o + 2 * H) * H;

    for (int i = tid; i < B * H; i += 256) {
        int b = i >> 9, k = i & 511;
        HS(k, b) = g_xc[b][k];
    }
    __syncthreads();

    int k0 = half * 256;
    float ar = 0.f, az = 0.f, an = 0.f;
    #pragma unroll 8
    for (int kk = 0; kk < 256; kk += 4) {
        int k = k0 + kk;
        float x0 = HS(k, lane), x1 = HS(k + 1, lane);
        float x2 = HS(k + 2, lane), x3 = HS(k + 3, lane);
        float4 u;
        u = *reinterpret_cast<const float4*>(wr + k);
        ar += u.x * x0 + u.y * x1 + u.z * x2 + u.w * x3;
        u = *reinterpret_cast<const float4*>(wz + k);
        az += u.x * x0 + u.y * x1 + u.z * x2 + u.w * x3;
        u = *reinterpret_cast<const float4*>(wn + k);
        an += u.x * x0 + u.y * x1 + u.z * x2 + u.w * x3;
    }
    SP(0, w, lane) = ar;
    SP(1, w, lane) = az;
    SP(2, w, lane) = an;
    __syncthreads();
    if (tid < 128) {
        int b = tid & 31, ol = tid >> 5;
        int oo = blockIdx.x * 4 + ol;
        float ir  = SP(0, ol, b) + SP(0, ol + 4, b) + b_ih[oo];
        float iz  = SP(1, ol, b) + SP(1, ol + 4, b) + b_ih[oo + H];
        float inn = SP(2, ol, b) + SP(2, ol + 4, b) + b_ih[oo + 2 * H];
        float r  = 1.f / (1.f + expf(-(ir + g_gh[b][oo])));
        float zz = 1.f / (1.f + expf(-(iz + g_gh[b][oo + H])));
        float n  = tanhf(inn + r * g_gh[b][oo + 2 * H]);
        float hp = g_h[cur][b][oo];
        float hn = (1.f - zz) * n + zz * hp;
        g_h[cur ^ 1][b][oo] = hn;
        if (t == TOUT - 1) d_out[OFF_HT + (size_t)b * H + oo] = hn;
    }
}

// ============================================================================
// KC: z = h_new @ W_out^T + b_out  (f32x2; 256 thr; VPB=256; single wave)
//   thread tile: 8 b x 4 v  (hv broadcast-heavy -> crossbar relief)
//   warp (bq, vh): b in {bq+4j}, v-half vh
//   2-stage cp.async; __stcs zbuf stores; last-block merge -> tok, logZ[t]
// ============================================================================
__device__ __forceinline__ void kc_issue(int buf, int kc, int tid, int vblk,
                                         const float* __restrict__ W_out,
                                         const float* __restrict__ hptr,
                                         ulonglong2* wsm, ulonglong2* hsm) {
    // wsm stage layout: [kq][vl]  (8 x 256)
    #pragma unroll
    for (int p = 0; p < 8; p++) {
        int idx = p * 256 + tid;
        int vl = idx & 255, kq = idx >> 8;
        cpa16(sm_u32(&wsm[(size_t)buf * 2048 + kq * 256 + vl]),
              W_out + (size_t)(vblk + vl) * H + kc + 4 * kq);
    }
    {
        int bb = tid >> 3, kq = tid & 7;
        cpa16(sm_u32(&hsm[(size_t)buf * 256 + bb * 8 + kq]),
              hptr + (size_t)bb * H + kc + 4 * kq);
    }
    asm volatile("cp.async.commit_group;");
}

extern "C" __global__ void __launch_bounds__(256)
kc_kernel(int t, int hidx, const float* __restrict__ W_out,
          const float* __restrict__ b_out) {
    extern __shared__ char dsm[];
    ulonglong2* wsm = reinterpret_cast<ulonglong2*>(dsm);             // 2*32KB
    ulonglong2* hsm = reinterpret_cast<ulonglong2*>(dsm + 2 * 32768); // 2*4KB
    __shared__ float s2m[2][B], s2s[2][B], s2v[2][B];
    __shared__ int   s2i[2][B];
    __shared__ unsigned s_last;
    __shared__ float sm_m[8][B], sm_s[8][B], sm_av[8][B];
    __shared__ int   sm_ai[8][B];

    int tid = threadIdx.x;
    int lane = tid & 31, wid = tid >> 5;
    int bq = wid & 3;          // b = bq + 4j
    int vh = wid >> 2;         // v-half (0/1)
    int vblk = blockIdx.x * VPB;
    int vbase = vblk + vh * 128;
    const float* hptr = &g_h[hidx][0][0];

    unsigned long long acc[8][4];
    #pragma unroll
    for (int j = 0; j < 8; j++)
        #pragma unroll
        for (int i = 0; i < 4; i++) acc[j][i] = 0ull;

    kc_issue(0, 0, tid, vblk, W_out, hptr, wsm, hsm);

    for (int c = 0; c < 16; c++) {
        int buf = c & 1;
        if (c < 15) {
            kc_issue(buf ^ 1, (c + 1) * 32, tid, vblk, W_out, hptr, wsm, hsm);
            asm volatile("cp.async.wait_group 1;");
        } else {
            asm volatile("cp.async.wait_group 0;");
        }
        __syncthreads();
        ulonglong2* wstage = wsm + (size_t)buf * 2048;
        ulonglong2* hstage = hsm + (size_t)buf * 256;
        #pragma unroll
        for (int kq = 0; kq < 8; kq++) {
            ulonglong2 hv[8];
            #pragma unroll
            for (int j = 0; j < 8; j++) hv[j] = hstage[(bq + 4 * j) * 8 + kq]; // bcast
            #pragma unroll
            for (int i = 0; i < 4; i++) {
                ulonglong2 wv = wstage[kq * 256 + vh * 128 + lane + 32 * i];
                #pragma unroll
                for (int j = 0; j < 8; j++) {
                    acc[j][i] = fma2(hv[j].x, wv.x, acc[j][i]);
                    acc[j][i] = fma2(hv[j].y, wv.y, acc[j][i]);
                }
            }
        }
        __syncthreads();
    }

    float bo[4];
    #pragma unroll
    for (int i = 0; i < 4; i++) bo[i] = b_out[vbase + lane + 32 * i];

    #pragma unroll
    for (int j = 0; j < 8; j++) {
        int b = bq + 4 * j;
        float zv[4];
        float lmax = -INFINITY;
        int lidx = 0;
        #pragma unroll
        for (int i = 0; i < 4; i++) {
            float lo, hi;
            upk(acc[j][i], lo, hi);
            int v = vbase + lane + 32 * i;
            float z = lo + hi + bo[i];
            zv[i] = z;
            __stcs(&g_zbuf[((size_t)t * B + b) * V + v], z);
            if (z > lmax) { lmax = z; lidx = v; }  // v ascending: first occurrence
        }
        float wm = lmax;
        int wi = lidx;
        #pragma unroll
        for (int off = 16; off; off >>= 1) {
            float om = __shfl_xor_sync(0xffffffffu, wm, off);
            int   oi = __shfl_xor_sync(0xffffffffu, wi, off);
            if (om > wm || (om == wm && oi < wi)) { wm = om; wi = oi; }
        }
        float ls = 0.f;
        #pragma unroll
        for (int i = 0; i < 4; i++) ls += expf(zv[i] - wm);
        #pragma unroll
        for (int off = 16; off; off >>= 1)
            ls += __shfl_xor_sync(0xffffffffu, ls, off);
        if (lane == 0) {
            s2m[vh][b] = wm; s2s[vh][b] = ls; s2v[vh][b] = wm; s2i[vh][b] = wi;
        }
    }
    __syncthreads();
    if (tid < B) {
        int b = tid;
        float m0 = s2m[0][b], m1 = s2m[1][b];
        float M = fmaxf(m0, m1);
        float S = s2s[0][b] * expf(m0 - M) + s2s[1][b] * expf(m1 - M);
        int   I; float AV;
        if (m0 >= m1) { AV = m0; I = s2i[0][b]; }   // vh=0 has lower v: ties -> lower
        else          { AV = m1; I = s2i[1][b]; }
        (void)AV;
        g_pmax[blockIdx.x][b] = M;
        g_psum[blockIdx.x][b] = S;
        g_pidx[blockIdx.x][b] = I;
    }

    // ---- last-block merge: tok for next step + logZ[t] ----
    __threadfence();
    __syncthreads();
    if (tid == 0) s_last = atomicAdd(&g_cnt, 1u);
    __syncthreads();
    if (s_last == NPB - 1) {
        __threadfence();
        int b = tid & 31, part = tid >> 5;   // 8 parts
        float m = -INFINITY, s = 0.f, av = -INFINITY;
        int ai = INT_MAX;
        for (int i = part; i < NPB; i += 8) {
            float pm = g_pmax[i][b];
            float ps = g_psum[i][b];
            int   pi = g_pidx[i][b];
            if (pm > m) { s = s * expf(m - pm) + ps; m = pm; }
            else        { s += ps * expf(pm - m); }
            if (pm > av || (pm == av && pi < ai)) { av = pm; ai = pi; }
        }
        sm_m[part][b] = m; sm_s[part][b] = s; sm_av[part][b] = av; sm_ai[part][b] = ai;
        __syncthreads();
        if (tid < B) {
            float M = -INFINITY, S = 0.f, AV = -INFINITY;
            int AI = INT_MAX;
            #pragma unroll
            for (int p = 0; p < 8; p++) {
                float pm = sm_m[p][tid], ps = sm_s[p][tid];
                if (pm > M) { S = S * expf(M - pm) + ps; M = pm; }
                else        { S += ps * expf(pm - M); }
                float v2 = sm_av[p][tid]; int i2 = sm_ai[p][tid];
                if (v2 > AV || (v2 == AV && i2 < AI)) { AV = v2; AI = i2; }
            }
            g_tok[tid] = AI;
            g_logZ[t][tid] = M + logf(S);
        }
        if (tid == 0) g_cnt = 0u;
    }
}

// ============================================================================
// E2: out[b][v][t] = z[t][b][v] - logZ[t][b]   (smem-tiled transpose)
// ============================================================================
extern "C" __global__ void __launch_bounds__(256)
e2_kernel(float* __restrict__ d_out) {
    __shared__ float s_z[128][52];
    __shared__ float s_lz[TOUT];
    int b = blockIdx.y;
    int v0 = blockIdx.x * 128;
    int tid = threadIdx.x;
    if (tid < TOUT) s_lz[tid] = g_logZ[tid][b];
    __syncthreads();
    for (int j = tid; j < 128 * TOUT; j += 256) {
        int tt = j >> 7, vl = j & 127;
        s_z[vl][tt] = g_zbuf[((size_t)tt * B + b) * V + v0 + vl] - s_lz[tt];
    }
    __syncthreads();
    size_t base = ((size_t)b * V + v0) * TOUT;
    for (int j = tid; j < 128 * TOUT; j += 256) {
        int vl = j / TOUT, tt = j % TOUT;
        d_out[base + j] = s_z[vl][tt];
    }
}

// ============================================================================
extern "C" void kernel_launch(void* const* d_in, const int* in_sizes, int n_in,
                              void* d_out_v, int out_size) {
    const float* enc    = (const float*)d_in[0];
    const int*   y      = (const int*)d_in[1];
    const float* emb    = (const float*)d_in[2];
    // d_in[3..6]: W_fc, b_fc, W_fc1, W_fc2 — dead (softmax over singleton axis)
    const float* W_comb = (const float*)d_in[7];
    const float* b_comb = (const float*)d_in[8];
    const float* W_ih   = (const float*)d_in[9];
    const float* W_hh   = (const float*)d_in[10];
    const float* b_ih   = (const float*)d_in[11];
    const float* b_hh   = (const float*)d_in[12];
    const float* W_out  = (const float*)d_in[13];
    const float* b_out  = (const float*)d_in[14];
    float* d_out = (float*)d_out_v;

    const int k1_smem = 512 * 33 * 4;                  // 67584
    const int k2_smem = (512 * 33 + 3 * 8 * 33) * 4;   // 70752
    const int kc_smem = 2 * 32768 + 2 * 4096;          // 73728
    cudaFuncSetAttribute(k1_kernel, cudaFuncAttributeMaxDynamicSharedMemorySize, k1_smem);
    cudaFuncSetAttribute(k2_kernel, cudaFuncAttributeMaxDynamicSharedMemorySize, k2_smem);
    cudaFuncSetAttribute(kc_kernel, cudaFuncAttributeMaxDynamicSharedMemorySize, kc_smem);

    p1_kernel<<<512, 256>>>(enc, y, d_out);
    p2_kernel<<<32, 256>>>(W_comb, b_comb);
    for (int t = 0; t < TOUT; t++) {
        int cur = t & 1;
        k1_kernel<<<128, 256, k1_smem>>>(cur, emb, W_comb, W_hh, b_hh);
        k2_kernel<<<128, 256, k2_smem>>>(t, cur, W_ih, b_ih, d_out);
        kc_kernel<<<NPB, 256, kc_smem>>>(t, cur ^ 1, W_out, b_out);
    }
    e2_kernel<<<dim3(V / 128, B), 256>>>(d_out);
}

// round 6
// speedup vs baseline: 2.6156x; 1.1336x over previous
#include <cuda_runtime.h>
#include <math.h>
#include <stdint.h>
#include <limits.h>

#define B    32
#define H    512
#define V    32000
#define TIN  50
#define TOUT 50
#define GRID 128      // persistent blocks (1/SM, all co-resident)
#define NPB  125      // projection blocks (V / VPB)
#define VPB  256      // v-columns per projection block

#define OFF_HT   ((size_t)B * V * TOUT)          // 51,200,000
#define OFF_ATTN (OFF_HT + (size_t)B * H)        // 51,216,384

// ---------------- device scratch (static, allowed) ----------------
__device__ float g_zbuf[(size_t)TOUT * B * V];   // raw logits, 204.8 MB
__device__ float g_pmax[NPB][B];
__device__ float g_psum[NPB][B];
__device__ int   g_pidx[NPB][B];
__device__ float g_logZ[TOUT][B];
__device__ float g_h[2][B][H];
__device__ float g_xc[B][H];
__device__ float g_gh[B][3 * H];
__device__ float g_attnx[B][H];
__device__ float g_cattn[B][H];
__device__ int   g_tok[B];
__device__ unsigned g_bar_cnt;                   // zero-init; returns to 0
__device__ volatile unsigned g_bar_gen;          // monotonic generation

// ---------------- helpers ----------------
__device__ __forceinline__ unsigned long long fma2(unsigned long long a,
                                                   unsigned long long b,
                                                   unsigned long long c) {
    unsigned long long d;
    asm("fma.rn.f32x2 %0, %1, %2, %3;" : "=l"(d) : "l"(a), "l"(b), "l"(c));
    return d;
}
__device__ __forceinline__ void upk(unsigned long long v, float& lo, float& hi) {
    asm("mov.b64 {%0, %1}, %2;" : "=f"(lo), "=f"(hi) : "l"(v));
}
__device__ __forceinline__ unsigned sm_u32(const void* p) {
    return (unsigned)__cvta_generic_to_shared(p);
}
__device__ __forceinline__ void cpa16(unsigned d, const void* s) {
    asm volatile("cp.async.cg.shared.global [%0], [%1], 16;" :: "r"(d), "l"(s));
}

// Device-wide barrier (all GRID blocks co-resident). Returns gen+1.
__device__ __forceinline__ unsigned gsync(unsigned gen) {
    __threadfence();
    __syncthreads();
    if (threadIdx.x == 0) {
        unsigned arr = atomicAdd(&g_bar_cnt, 1u);
        if (arr == GRID - 1) {
            g_bar_cnt = 0u;
            __threadfence();
            g_bar_gen = gen + 1u;
        } else {
            while (g_bar_gen != gen + 1u) { __nanosleep(32); }
        }
    }
    __syncthreads();
    return gen + 1u;
}

// ============================================================================
// P1: attn_x = sum_t encoder_out ; h0 = 0 ; attn output = ones ; tok0
// ============================================================================
extern "C" __global__ void p1_kernel(const float* __restrict__ enc,
                                     const int* __restrict__ y,
                                     float* __restrict__ d_out) {
    int gid  = blockIdx.x * blockDim.x + threadIdx.x;
    int nthr = gridDim.x * blockDim.x;
    if (gid < B) g_tok[gid] = y[gid * TOUT];     // y[b][0]
    for (int i = gid; i < B * H; i += nthr) {
        int b = i >> 9, k = i & 511;
        g_h[0][b][k] = 0.f;
        float s = 0.f;
        #pragma unroll 5
        for (int tt = 0; tt < TIN; tt++) s += enc[((size_t)b * TIN + tt) * H + k];
        g_attnx[b][k] = s;
    }
    float4 one4 = make_float4(1.f, 1.f, 1.f, 1.f);
    float4* dst = reinterpret_cast<float4*>(d_out + OFF_ATTN);
    size_t n4 = (size_t)TOUT * B * TIN * H / 4;
    for (size_t i = gid; i < n4; i += nthr) dst[i] = one4;
}

// ============================================================================
// MAIN persistent kernel: prologue (c_attn) + 50 x [A | B | C] + final logZ
// ============================================================================
#define HS(k, b) hs[(k) * 33 + (b)]
#define SP(g, ww, l) sp[((g) * 8 + (ww)) * 33 + (l)]

extern "C" __global__ void __launch_bounds__(256, 1)
main_kernel(const float* __restrict__ emb,
            const float* __restrict__ W_comb, const float* __restrict__ b_comb,
            const float* __restrict__ W_hh,  const float* __restrict__ b_hh,
            const float* __restrict__ W_ih,  const float* __restrict__ b_ih,
            const float* __restrict__ W_out, const float* __restrict__ b_out,
            float* __restrict__ d_out) {
    extern __shared__ char dsm[];
    float* hs = reinterpret_cast<float*>(dsm);                   // A/B staging
    float* sp = reinterpret_cast<float*>(dsm) + 512 * 33;        // B reduce
    ulonglong2* wsm = reinterpret_cast<ulonglong2*>(dsm);        // C: 64 KB
    ulonglong2* hsm = reinterpret_cast<ulonglong2*>(dsm + 65536);// C:  8 KB

    __shared__ int   s_tok[B];
    __shared__ float sm_m[8][B], sm_s[8][B], sm_av[8][B];
    __shared__ int   sm_ai[8][B];
    __shared__ float s2m[2][B], s2s[2][B];
    __shared__ int   s2i[2][B];

    int tid = threadIdx.x, bid = blockIdx.x;
    int lane = tid & 31, w = tid >> 5;
    unsigned gen = g_bar_gen;   // stable until all blocks arrive at barrier 1

    // ---------------- prologue: c_attn (blocks 0..31) ----------------
    if (bid < 32) {
        for (int i = tid; i < B * H; i += 256) {
            int b = i >> 9, k = i & 511;
            HS(k, b) = g_attnx[b][k];
        }
        __syncthreads();
        int o0 = bid * 16 + w * 2;
        const float* r0 = W_comb + (size_t)o0 * (2 * H) + H;
        const float* r1 = r0 + 2 * H;
        float a0 = 0.f, a1 = 0.f;
        #pragma unroll 8
        for (int k = 0; k < H; k += 4) {
            float4 u0 = *reinterpret_cast<const float4*>(r0 + k);
            float4 u1 = *reinterpret_cast<const float4*>(r1 + k);
            float x0 = HS(k, lane), x1 = HS(k + 1, lane);
            float x2 = HS(k + 2, lane), x3 = HS(k + 3, lane);
            a0 += u0.x * x0 + u0.y * x1 + u0.z * x2 + u0.w * x3;
            a1 += u1.x * x0 + u1.y * x1 + u1.z * x2 + u1.w * x3;
        }
        g_cattn[lane][o0]     = a0 + b_comb[o0];
        g_cattn[lane][o0 + 1] = a1 + b_comb[o0 + 1];
    }
    gen = gsync(gen);

    int cur = 0;
    for (int t = 0; t < TOUT; t++) {
        // ================= Phase A: merge->tok, xc, gh =================
        {
            bool is_xc = (bid < 32);
            if (is_xc) {
                if (t > 0) {
                    int b = lane, part = w;
                    float m = -INFINITY, s = 0.f, av = -INFINITY;
                    int ai = INT_MAX;
                    for (int i = part; i < NPB; i += 8) {
                        float pm = g_pmax[i][b];
                        float ps = g_psum[i][b];
                        int   pi = g_pidx[i][b];
                        if (pm > m) { s = s * expf(m - pm) + ps; m = pm; }
                        else        { s += ps * expf(pm - m); }
                        if (pm > av || (pm == av && pi < ai)) { av = pm; ai = pi; }
                    }
                    sm_m[part][b] = m; sm_s[part][b] = s;
                    sm_av[part][b] = av; sm_ai[part][b] = ai;
                    __syncthreads();
                    if (tid < B) {
                        float M = -INFINITY, S = 0.f, AV = -INFINITY;
                        int AI = INT_MAX;
                        #pragma unroll
                        for (int p = 0; p < 8; p++) {
                            float pm = sm_m[p][tid], ps = sm_s[p][tid];
                            if (pm > M) { S = S * expf(M - pm) + ps; M = pm; }
                            else        { S += ps * expf(pm - M); }
                            float v2 = sm_av[p][tid]; int i2 = sm_ai[p][tid];
                            if (v2 > AV || (v2 == AV && i2 < AI)) { AV = v2; AI = i2; }
                        }
                        s_tok[tid] = AI;
                        if (bid == 0) g_logZ[t - 1][tid] = M + logf(S);
                    }
                } else {
                    if (tid < B) s_tok[tid] = g_tok[tid];
                }
                __syncthreads();
            }

            int o0 = (is_xc ? bid * 16 : (bid - 32) * 16) + w * 2;
            const float* r0 = is_xc ? (W_comb + (size_t)o0 * (2 * H))
                                    : (W_hh + (size_t)o0 * H);
            const float* r1 = is_xc ? (r0 + 2 * H) : (r0 + H);

            for (int i = tid; i < B * H; i += 256) {
                int b = i >> 9, k = i & 511;
                HS(k, b) = is_xc ? emb[(size_t)s_tok[b] * H + k]
                                 : g_h[cur][b][k];
            }
            __syncthreads();

            float a0a = 0.f, a0b = 0.f, a1a = 0.f, a1b = 0.f;
            #pragma unroll 8
            for (int k = 0; k < H; k += 4) {
                float4 u0 = *reinterpret_cast<const float4*>(r0 + k);
                float4 u1 = *reinterpret_cast<const float4*>(r1 + k);
                float x0 = HS(k, lane), x1 = HS(k + 1, lane);
                float x2 = HS(k + 2, lane), x3 = HS(k + 3, lane);
                a0a += u0.x * x0 + u0.y * x1;  a0b += u0.z * x2 + u0.w * x3;
                a1a += u1.x * x0 + u1.y * x1;  a1b += u1.z * x2 + u1.w * x3;
            }
            float v0 = a0a + a0b, v1 = a1a + a1b;
            if (is_xc) {
                v0 += g_cattn[lane][o0];
                v1 += g_cattn[lane][o0 + 1];
                g_xc[lane][o0]     = v0 > 0.f ? v0 : 0.f;
                g_xc[lane][o0 + 1] = v1 > 0.f ? v1 : 0.f;
            } else {
                g_gh[lane][o0]     = v0 + b_hh[o0];
                g_gh[lane][o0 + 1] = v1 + b_hh[o0 + 1];
            }
        }
        gen = gsync(gen);

        // ================= Phase B: gi + GRU -> h_new =================
        {
            int o_l = w & 3, half = w >> 2;
            int o = bid * 4 + o_l;
            const float* wr = W_ih + (size_t)o * H;
            const float* wz = W_ih + (size_t)(o + H) * H;
            const float* wn = W_ih + (size_t)(o + 2 * H) * H;

            for (int i = tid; i < B * H; i += 256) {
                int b = i >> 9, k = i & 511;
                HS(k, b) = g_xc[b][k];
            }
            __syncthreads();

            int k0 = half * 256;
            float ar = 0.f, az = 0.f, an = 0.f;
            #pragma unroll 8
            for (int kk = 0; kk < 256; kk += 4) {
                int k = k0 + kk;
                float x0 = HS(k, lane), x1 = HS(k + 1, lane);
                float x2 = HS(k + 2, lane), x3 = HS(k + 3, lane);
                float4 u;
                u = *reinterpret_cast<const float4*>(wr + k);
                ar += u.x * x0 + u.y * x1 + u.z * x2 + u.w * x3;
                u = *reinterpret_cast<const float4*>(wz + k);
                az += u.x * x0 + u.y * x1 + u.z * x2 + u.w * x3;
                u = *reinterpret_cast<const float4*>(wn + k);
                an += u.x * x0 + u.y * x1 + u.z * x2 + u.w * x3;
            }
            SP(0, w, lane) = ar;
            SP(1, w, lane) = az;
            SP(2, w, lane) = an;
            __syncthreads();
            if (tid < 128) {
                int b = tid & 31, ol = tid >> 5;
                int oo = bid * 4 + ol;
                float ir  = SP(0, ol, b) + SP(0, ol + 4, b) + b_ih[oo];
                float iz  = SP(1, ol, b) + SP(1, ol + 4, b) + b_ih[oo + H];
                float inn = SP(2, ol, b) + SP(2, ol + 4, b) + b_ih[oo + 2 * H];
                float r  = 1.f / (1.f + expf(-(ir + g_gh[b][oo])));
                float zz = 1.f / (1.f + expf(-(iz + g_gh[b][oo + H])));
                float n  = tanhf(inn + r * g_gh[b][oo + 2 * H]);
                float hp = g_h[cur][b][oo];
                float hn = (1.f - zz) * n + zz * hp;
                g_h[cur ^ 1][b][oo] = hn;
                if (t == TOUT - 1) d_out[OFF_HT + (size_t)b * H + oo] = hn;
            }
        }
        gen = gsync(gen);

        // ================= Phase C: logits + partial softmax/argmax ====
        if (bid < NPB) {
            int bq = w & 3;            // b = bq + 4j
            int vh = w >> 2;           // v-half
            int vblk = bid * VPB;
            int vbase = vblk + vh * 128;
            const float* hptr = &g_h[cur ^ 1][0][0];

            unsigned long long acc[8][4];
            #pragma unroll
            for (int j = 0; j < 8; j++)
                #pragma unroll
                for (int i = 0; i < 4; i++) acc[j][i] = 0ull;

            // stage 0 issue
            {
                #pragma unroll
                for (int p = 0; p < 8; p++) {
                    int idx = p * 256 + tid;
                    int vl = idx & 255, kq = idx >> 8;
                    cpa16(sm_u32(&wsm[kq * 256 + vl]),
                          W_out + (size_t)(vblk + vl) * H + 4 * kq);
                }
                int bb = tid >> 3, kq = tid & 7;
                cpa16(sm_u32(&hsm[bb * 8 + kq]), hptr + (size_t)bb * H + 4 * kq);
                asm volatile("cp.async.commit_group;");
            }

            for (int c = 0; c < 16; c++) {
                int buf = c & 1;
                if (c < 15) {
                    int kc = (c + 1) * 32, nb = buf ^ 1;
                    #pragma unroll
                    for (int p = 0; p < 8; p++) {
                        int idx = p * 256 + tid;
                        int vl = idx & 255, kq = idx >> 8;
                        cpa16(sm_u32(&wsm[(size_t)nb * 2048 + kq * 256 + vl]),
                              W_out + (size_t)(vblk + vl) * H + kc + 4 * kq);
                    }
                    int bb = tid >> 3, kq = tid & 7;
                    cpa16(sm_u32(&hsm[(size_t)nb * 256 + bb * 8 + kq]),
                          hptr + (size_t)bb * H + kc + 4 * kq);
                    asm volatile("cp.async.commit_group;");
                    asm volatile("cp.async.wait_group 1;");
                } else {
                    asm volatile("cp.async.wait_group 0;");
                }
                __syncthreads();
                ulonglong2* wstage = wsm + (size_t)buf * 2048;
                ulonglong2* hstage = hsm + (size_t)buf * 256;
                #pragma unroll
                for (int kq = 0; kq < 8; kq++) {
                    ulonglong2 hv[8];
                    #pragma unroll
                    for (int j = 0; j < 8; j++) hv[j] = hstage[(bq + 4 * j) * 8 + kq];
                    #pragma unroll
                    for (int i = 0; i < 4; i++) {
                        ulonglong2 wv = wstage[kq * 256 + vh * 128 + lane + 32 * i];
                        #pragma unroll
                        for (int j = 0; j < 8; j++) {
                            acc[j][i] = fma2(hv[j].x, wv.x, acc[j][i]);
                            acc[j][i] = fma2(hv[j].y, wv.y, acc[j][i]);
                        }
                    }
                }
                __syncthreads();
            }

            float bo[4];
            #pragma unroll
            for (int i = 0; i < 4; i++) bo[i] = b_out[vbase + lane + 32 * i];

            #pragma unroll
            for (int j = 0; j < 8; j++) {
                int b = bq + 4 * j;
                float zv[4];
                float lmax = -INFINITY;
                int lidx = 0;
                #pragma unroll
                for (int i = 0; i < 4; i++) {
                    float lo, hi;
                    upk(acc[j][i], lo, hi);
                    int v = vbase + lane + 32 * i;
                    float z = lo + hi + bo[i];
                    zv[i] = z;
                    __stcs(&g_zbuf[((size_t)t * B + b) * V + v], z);
                    if (z > lmax) { lmax = z; lidx = v; }
                }
                float wm = lmax;
                int wi = lidx;
                #pragma unroll
                for (int off = 16; off; off >>= 1) {
                    float om = __shfl_xor_sync(0xffffffffu, wm, off);
                    int   oi = __shfl_xor_sync(0xffffffffu, wi, off);
                    if (om > wm || (om == wm && oi < wi)) { wm = om; wi = oi; }
                }
                float ls = 0.f;
                #pragma unroll
                for (int i = 0; i < 4; i++) ls += expf(zv[i] - wm);
                #pragma unroll
                for (int off = 16; off; off >>= 1)
                    ls += __shfl_xor_sync(0xffffffffu, ls, off);
                if (lane == 0) {
                    s2m[vh][b] = wm; s2s[vh][b] = ls; s2i[vh][b] = wi;
                }
            }
            __syncthreads();
            if (tid < B) {
                int b = tid;
                float m0 = s2m[0][b], m1 = s2m[1][b];
                float M = fmaxf(m0, m1);
                float S = s2s[0][b] * expf(m0 - M) + s2s[1][b] * expf(m1 - M);
                int I = (m0 >= m1) ? s2i[0][b] : s2i[1][b];  // ties -> lower v
                g_pmax[bid][b] = M;
                g_psum[bid][b] = S;
                g_pidx[bid][b] = I;
            }
        }
        gen = gsync(gen);
        cur ^= 1;
    }

    // ---------------- final logZ[TOUT-1] (block 0) ----------------
    if (bid == 0) {
        int b = lane, part = w;
        float m = -INFINITY, s = 0.f;
        for (int i = part; i < NPB; i += 8) {
            float pm = g_pmax[i][b], ps = g_psum[i][b];
            if (pm > m) { s = s * expf(m - pm) + ps; m = pm; }
            else        { s += ps * expf(pm - m); }
        }
        sm_m[part][b] = m; sm_s[part][b] = s;
        __syncthreads();
        if (tid < B) {
            float M = -INFINITY, S = 0.f;
            #pragma unroll
            for (int p = 0; p < 8; p++) {
                float pm = sm_m[p][tid], ps = sm_s[p][tid];
                if (pm > M) { S = S * expf(M - pm) + ps; M = pm; }
                else        { S += ps * expf(pm - M); }
            }
            g_logZ[TOUT - 1][tid] = M + logf(S);
        }
    }
}

// ============================================================================
// E2: out[b][v][t] = z[t][b][v] - logZ[t][b]   (smem-tiled transpose)
// ============================================================================
extern "C" __global__ void __launch_bounds__(256)
e2_kernel(float* __restrict__ d_out) {
    __shared__ float s_z[128][52];
    __shared__ float s_lz[TOUT];
    int b = blockIdx.y;
    int v0 = blockIdx.x * 128;
    int tid = threadIdx.x;
    if (tid < TOUT) s_lz[tid] = g_logZ[tid][b];
    __syncthreads();
    for (int j = tid; j < 128 * TOUT; j += 256) {
        int tt = j >> 7, vl = j & 127;
        s_z[vl][tt] = g_zbuf[((size_t)tt * B + b) * V + v0 + vl] - s_lz[tt];
    }
    __syncthreads();
    size_t base = ((size_t)b * V + v0) * TOUT;
    for (int j = tid; j < 128 * TOUT; j += 256) {
        int vl = j / TOUT, tt = j % TOUT;
        d_out[base + j] = s_z[vl][tt];
    }
}

// ============================================================================
extern "C" void kernel_launch(void* const* d_in, const int* in_sizes, int n_in,
                              void* d_out_v, int out_size) {
    const float* enc    = (const float*)d_in[0];
    const int*   y      = (const int*)d_in[1];
    const float* emb    = (const float*)d_in[2];
    // d_in[3..6]: W_fc, b_fc, W_fc1, W_fc2 — dead (softmax over singleton axis)
    const float* W_comb = (const float*)d_in[7];
    const float* b_comb = (const float*)d_in[8];
    const float* W_ih   = (const float*)d_in[9];
    const float* W_hh   = (const float*)d_in[10];
    const float* b_ih   = (const float*)d_in[11];
    const float* b_hh   = (const float*)d_in[12];
    const float* W_out  = (const float*)d_in[13];
    const float* b_out  = (const float*)d_in[14];
    float* d_out = (float*)d_out_v;

    const int main_smem = 2 * 32768 + 2 * 4096;        // 73728 (union of phases)
    cudaFuncSetAttribute(main_kernel, cudaFuncAttributeMaxDynamicSharedMemorySize,
                         main_smem);

    p1_kernel<<<512, 256>>>(enc, y, d_out);
    main_kernel<<<GRID, 256, main_smem>>>(emb, W_comb, b_comb, W_hh, b_hh,
                                          W_ih, b_ih, W_out, b_out, d_out);
    e2_kernel<<<dim3(V / 128, B), 256>>>(d_out);
}

// round 7
// speedup vs baseline: 3.0943x; 1.1830x over previous
#include <cuda_runtime.h>
#include <math.h>
#include <stdint.h>
#include <limits.h>

#define B    32
#define H    512
#define V    32000
#define TIN  50
#define TOUT 50
#define GRID 128      // persistent blocks (1/SM, all co-resident)
#define NPB  125      // projection blocks (V / VPB)
#define VPB  256      // v-columns per projection block
#define S_PAD 257     // input staging pad (pairs per b-row)

#define OFF_HT   ((size_t)B * V * TOUT)          // 51,200,000
#define OFF_ATTN (OFF_HT + (size_t)B * H)        // 51,216,384

typedef unsigned long long ull;

// ---------------- device scratch (static, allowed) ----------------
__device__ float g_zbuf[(size_t)TOUT * B * V];   // raw logits, 204.8 MB
__device__ float g_pmax[NPB][B];
__device__ float g_psum[NPB][B];
__device__ int   g_pidx[NPB][B];
__device__ float g_logZ[TOUT][B];
__device__ float g_h[2][B][H];
__device__ float g_xc[B][H];
__device__ float g_gh[B][3 * H];
__device__ float g_attnx[B][H];
__device__ float g_cattn[B][H];
__device__ int   g_tok[B];
__device__ unsigned g_bar_cnt;                   // monotonic
__device__ unsigned g_bar_gen;                   // monotonic

// ---------------- helpers ----------------
__device__ __forceinline__ ull fma2(ull a, ull b, ull c) {
    ull d;
    asm("fma.rn.f32x2 %0, %1, %2, %3;" : "=l"(d) : "l"(a), "l"(b), "l"(c));
    return d;
}
__device__ __forceinline__ void upk(ull v, float& lo, float& hi) {
    asm("mov.b64 {%0, %1}, %2;" : "=f"(lo), "=f"(hi) : "l"(v));
}
__device__ __forceinline__ float sum2(ull v) {
    float lo, hi; upk(v, lo, hi); return lo + hi;
}
__device__ __forceinline__ unsigned sm_u32(const void* p) {
    return (unsigned)__cvta_generic_to_shared(p);
}
__device__ __forceinline__ void cpa16(unsigned d, const void* s) {
    asm volatile("cp.async.cg.shared.global [%0], [%1], 16;" :: "r"(d), "l"(s));
}

// Device-wide barrier: monotonic release/acquire (all GRID blocks co-resident).
__device__ __forceinline__ unsigned gsync(unsigned gen) {
    __syncthreads();
    if (threadIdx.x == 0) {
        unsigned next = gen + 1u;
        unsigned old;
        asm volatile("atom.release.gpu.global.add.u32 %0, [%1], %2;"
                     : "=r"(old) : "l"(&g_bar_cnt), "r"(1u) : "memory");
        if (old == next * GRID - 1u) {
            asm volatile("st.release.gpu.global.u32 [%0], %1;"
                         :: "l"(&g_bar_gen), "r"(next) : "memory");
        } else {
            unsigned cur;
            do {
                __nanosleep(32);
                asm volatile("ld.acquire.gpu.global.u32 %0, [%1];"
                             : "=r"(cur) : "l"(&g_bar_gen) : "memory");
            } while ((int)(cur - next) < 0);
        }
    }
    __syncthreads();
    return gen + 1u;
}

// ============================================================================
// P1: attn_x = sum_t encoder_out ; h0 = 0 ; attn output = ones ; tok0
// ============================================================================
extern "C" __global__ void p1_kernel(const float* __restrict__ enc,
                                     const int* __restrict__ y,
                                     float* __restrict__ d_out) {
    int gid  = blockIdx.x * blockDim.x + threadIdx.x;
    int nthr = gridDim.x * blockDim.x;
    if (gid < B) g_tok[gid] = y[gid * TOUT];     // y[b][0]
    for (int i = gid; i < B * H; i += nthr) {
        int b = i >> 9, k = i & 511;
        g_h[0][b][k] = 0.f;
        float s = 0.f;
        #pragma unroll 5
        for (int tt = 0; tt < TIN; tt++) s += enc[((size_t)b * TIN + tt) * H + k];
        g_attnx[b][k] = s;
    }
    float4 one4 = make_float4(1.f, 1.f, 1.f, 1.f);
    float4* dst = reinterpret_cast<float4*>(d_out + OFF_ATTN);
    size_t n4 = (size_t)TOUT * B * TIN * H / 4;
    for (size_t i = gid; i < n4; i += nthr) dst[i] = one4;
}

// ============================================================================
// MAIN persistent kernel
//   smem union:
//     A/B/prologue: inp pairs [32][S_PAD] (65792 B) + wtile[2][16][64] (16384 B)
//     C:            wsm 64 KB + hsm 8 KB
// ============================================================================
extern "C" __global__ void __launch_bounds__(256, 1)
main_kernel(const float* __restrict__ emb,
            const float* __restrict__ W_comb, const float* __restrict__ b_comb,
            const float* __restrict__ W_hh,  const float* __restrict__ b_hh,
            const float* __restrict__ W_ih,  const float* __restrict__ b_ih,
            const float* __restrict__ W_out, const float* __restrict__ b_out,
            float* __restrict__ d_out) {
    extern __shared__ char dsm[];
    ull* inp = reinterpret_cast<ull*>(dsm);                       // [32][S_PAD]
    ull* wtile = reinterpret_cast<ull*>(dsm + 65792);             // [2][16][64]
    ulonglong2* wsm = reinterpret_cast<ulonglong2*>(dsm);         // C: 64 KB
    ulonglong2* hsm = reinterpret_cast<ulonglong2*>(dsm + 65536); // C:  8 KB

    __shared__ int   s_tok[B];
    __shared__ float sm_m[8][B], sm_s[8][B], sm_av[8][B];
    __shared__ int   sm_ai[8][B];
    __shared__ float s2m[2][B], s2s[2][B];
    __shared__ int   s2i[2][B];
    __shared__ float sp[12][33];

    int tid = threadIdx.x, bid = blockIdx.x;
    int lane = tid & 31, w = tid >> 5;
    unsigned gen;
    asm volatile("ld.acquire.gpu.global.u32 %0, [%1];" : "=r"(gen) : "l"(&g_bar_gen));

    // ============== prologue: c_attn (blocks 0..31, A-style) ==============
    if (bid < 32) {
        int row0 = bid * 16;
        const float* wbase = W_comb + H;       // attn-half of W_comb rows
        const size_t wstride = 2 * H;
        // issue W chunks 0,1
        #pragma unroll
        for (int cc = 0; cc < 2; cc++) {
            #pragma unroll
            for (int p = 0; p < 2; p++) {
                int idx = p * 256 + tid;
                int r = idx >> 5, jj = idx & 31;
                cpa16(sm_u32(&wtile[(size_t)cc * 1024 + r * 64 + jj * 2]),
                      wbase + (size_t)(row0 + r) * wstride + cc * 128 + jj * 4);
            }
            asm volatile("cp.async.commit_group;");
        }
        for (int i = tid; i < B * 256; i += 256) {
            int b = i >> 8, kq = i & 255;
            float2 v = *reinterpret_cast<const float2*>(&g_attnx[b][2 * kq]);
            *reinterpret_cast<float2*>(&inp[b * S_PAD + kq]) = v;
        }
        ull a00 = 0, a01 = 0, a10 = 0, a11 = 0;
        for (int c = 0; c < 4; c++) {
            if (c < 3) asm volatile("cp.async.wait_group 1;");
            else       asm volatile("cp.async.wait_group 0;");
            __syncthreads();
            const ull* wch = wtile + (size_t)(c & 1) * 1024;
            int r0 = (2 * w) * 64, r1 = (2 * w + 1) * 64;
            const ull* xrow = inp + lane * S_PAD + c * 64;
            #pragma unroll 8
            for (int q = 0; q < 64; q += 2) {
                ull x0 = xrow[q], x1 = xrow[q + 1];
                a00 = fma2(wch[r0 + q], x0, a00);
                a01 = fma2(wch[r0 + q + 1], x1, a01);
                a10 = fma2(wch[r1 + q], x0, a10);
                a11 = fma2(wch[r1 + q + 1], x1, a11);
            }
            __syncthreads();
            if (c < 2) {
                #pragma unroll
                for (int p = 0; p < 2; p++) {
                    int idx = p * 256 + tid;
                    int r = idx >> 5, jj = idx & 31;
                    cpa16(sm_u32(&wtile[(size_t)(c & 1) * 1024 + r * 64 + jj * 2]),
                          wbase + (size_t)(row0 + r) * wstride + (c + 2) * 128 + jj * 4);
                }
                asm volatile("cp.async.commit_group;");
            }
        }
        int o0 = row0 + 2 * w;
        g_cattn[lane][o0]     = sum2(a00) + sum2(a01) + b_comb[o0];
        g_cattn[lane][o0 + 1] = sum2(a10) + sum2(a11) + b_comb[o0 + 1];
    }
    gen = gsync(gen);

    int cur = 0;
    for (int t = 0; t < TOUT; t++) {
        // ========= Phase A: (xc blocks: merge->tok) + xc / gh GEMMs =========
        {
            bool is_xc = (bid < 32);
            int row0;
            const float* wbase;
            size_t wstride;
            if (is_xc) { row0 = bid * 16; wbase = W_comb; wstride = 2 * H; }
            else       { row0 = (bid - 32) * 16; wbase = W_hh; wstride = H; }

            // W prefetch (independent of tok/merge)
            #pragma unroll
            for (int cc = 0; cc < 2; cc++) {
                #pragma unroll
                for (int p = 0; p < 2; p++) {
                    int idx = p * 256 + tid;
                    int r = idx >> 5, jj = idx & 31;
                    cpa16(sm_u32(&wtile[(size_t)cc * 1024 + r * 64 + jj * 2]),
                          wbase + (size_t)(row0 + r) * wstride + cc * 128 + jj * 4);
                }
                asm volatile("cp.async.commit_group;");
            }

            if (is_xc) {
                if (t > 0) {
                    int b = lane, part = w;
                    float m = -INFINITY, s = 0.f, av = -INFINITY;
                    int ai = INT_MAX;
                    for (int i = part; i < NPB; i += 8) {
                        float pm = g_pmax[i][b];
                        float ps = g_psum[i][b];
                        int   pi = g_pidx[i][b];
                        if (pm > m) { s = s * expf(m - pm) + ps; m = pm; }
                        else        { s += ps * expf(pm - m); }
                        if (pm > av || (pm == av && pi < ai)) { av = pm; ai = pi; }
                    }
                    sm_m[part][b] = m; sm_s[part][b] = s;
                    sm_av[part][b] = av; sm_ai[part][b] = ai;
                    __syncthreads();
                    if (tid < B) {
                        float M = -INFINITY, S = 0.f, AV = -INFINITY;
                        int AI = INT_MAX;
                        #pragma unroll
                        for (int p = 0; p < 8; p++) {
                            float pm = sm_m[p][tid], ps = sm_s[p][tid];
                            if (pm > M) { S = S * expf(M - pm) + ps; M = pm; }
                            else        { S += ps * expf(pm - M); }
                            float v2 = sm_av[p][tid]; int i2 = sm_ai[p][tid];
                            if (v2 > AV || (v2 == AV && i2 < AI)) { AV = v2; AI = i2; }
                        }
                        s_tok[tid] = AI;
                        if (bid == 0) g_logZ[t - 1][tid] = M + logf(S);
                    }
                } else {
                    if (tid < B) s_tok[tid] = g_tok[tid];
                }
                __syncthreads();
            }

            for (int i = tid; i < B * 256; i += 256) {
                int b = i >> 8, kq = i & 255;
                const float* src = is_xc ? (emb + (size_t)s_tok[b] * H)
                                         : &g_h[cur][b][0];
                float2 v = *reinterpret_cast<const float2*>(src + 2 * kq);
                *reinterpret_cast<float2*>(&inp[b * S_PAD + kq]) = v;
            }

            ull a00 = 0, a01 = 0, a10 = 0, a11 = 0;
            for (int c = 0; c < 4; c++) {
                if (c < 3) asm volatile("cp.async.wait_group 1;");
                else       asm volatile("cp.async.wait_group 0;");
                __syncthreads();
                const ull* wch = wtile + (size_t)(c & 1) * 1024;
                int r0 = (2 * w) * 64, r1 = (2 * w + 1) * 64;
                const ull* xrow = inp + lane * S_PAD + c * 64;
                #pragma unroll 8
                for (int q = 0; q < 64; q += 2) {
                    ull x0 = xrow[q], x1 = xrow[q + 1];
                    a00 = fma2(wch[r0 + q], x0, a00);
                    a01 = fma2(wch[r0 + q + 1], x1, a01);
                    a10 = fma2(wch[r1 + q], x0, a10);
                    a11 = fma2(wch[r1 + q + 1], x1, a11);
                }
                __syncthreads();
                if (c < 2) {
                    #pragma unroll
                    for (int p = 0; p < 2; p++) {
                        int idx = p * 256 + tid;
                        int r = idx >> 5, jj = idx & 31;
                        cpa16(sm_u32(&wtile[(size_t)(c & 1) * 1024 + r * 64 + jj * 2]),
                              wbase + (size_t)(row0 + r) * wstride + (c + 2) * 128 + jj * 4);
                    }
                    asm volatile("cp.async.commit_group;");
                }
            }
            float v0 = sum2(a00) + sum2(a01);
            float v1 = sum2(a10) + sum2(a11);
            int o0 = row0 + 2 * w, o1 = o0 + 1;
            if (is_xc) {
                v0 += g_cattn[lane][o0];
                v1 += g_cattn[lane][o1];
                g_xc[lane][o0] = v0 > 0.f ? v0 : 0.f;
                g_xc[lane][o1] = v1 > 0.f ? v1 : 0.f;
            } else {
                g_gh[lane][o0] = v0 + b_hh[o0];
                g_gh[lane][o1] = v1 + b_hh[o1];
            }
        }
        gen = gsync(gen);

        // ========= Phase B: gi (12 rows/block: 3 gates x 4 o) + GRU =========
        {
            int obase = bid * 4;
            // W rows: rl = g*4 + ol -> W_ih row g*H + obase + ol
            #pragma unroll
            for (int cc = 0; cc < 2; cc++) {
                #pragma unroll
                for (int p = 0; p < 2; p++) {
                    int idx = p * 256 + tid;
                    if (idx < 384) {
                        int r = idx >> 5, jj = idx & 31;
                        int g = r >> 2, ol = r & 3;
                        cpa16(sm_u32(&wtile[(size_t)cc * 1024 + r * 64 + jj * 2]),
                              W_ih + (size_t)(g * H + obase + ol) * H + cc * 128 + jj * 4);
                    }
                }
                asm volatile("cp.async.commit_group;");
            }
            for (int i = tid; i < B * 256; i += 256) {
                int b = i >> 8, kq = i & 255;
                float2 v = *reinterpret_cast<const float2*>(&g_xc[b][2 * kq]);
                *reinterpret_cast<float2*>(&inp[b * S_PAD + kq]) = v;
            }
            ull a00 = 0, a01 = 0, a10 = 0, a11 = 0;
            for (int c = 0; c < 4; c++) {
                if (c < 3) asm volatile("cp.async.wait_group 1;");
                else       asm volatile("cp.async.wait_group 0;");
                __syncthreads();
                if (w < 6) {
                    const ull* wch = wtile + (size_t)(c & 1) * 1024;
                    int r0 = (2 * w) * 64, r1 = (2 * w + 1) * 64;
                    const ull* xrow = inp + lane * S_PAD + c * 64;
                    #pragma unroll 8
                    for (int q = 0; q < 64; q += 2) {
                        ull x0 = xrow[q], x1 = xrow[q + 1];
                        a00 = fma2(wch[r0 + q], x0, a00);
                        a01 = fma2(wch[r0 + q + 1], x1, a01);
                        a10 = fma2(wch[r1 + q], x0, a10);
                        a11 = fma2(wch[r1 + q + 1], x1, a11);
                    }
                }
                __syncthreads();
                if (c < 2) {
                    #pragma unroll
                    for (int p = 0; p < 2; p++) {
                        int idx = p * 256 + tid;
                        if (idx < 384) {
                            int r = idx >> 5, jj = idx & 31;
                            int g = r >> 2, ol = r & 3;
                            cpa16(sm_u32(&wtile[(size_t)(c & 1) * 1024 + r * 64 + jj * 2]),
                                  W_ih + (size_t)(g * H + obase + ol) * H + (c + 2) * 128 + jj * 4);
                        }
                    }
                    asm volatile("cp.async.commit_group;");
                }
            }
            if (w < 6) {
                sp[2 * w][lane]     = sum2(a00) + sum2(a01);
                sp[2 * w + 1][lane] = sum2(a10) + sum2(a11);
            }
            __syncthreads();
            if (tid < 128) {
                int b = tid & 31, ol = tid >> 5;
                int oo = obase + ol;
                float ir  = sp[ol][b]     + b_ih[oo];
                float iz  = sp[4 + ol][b] + b_ih[oo + H];
                float inn = sp[8 + ol][b] + b_ih[oo + 2 * H];
                float r  = 1.f / (1.f + expf(-(ir + g_gh[b][oo])));
                float zz = 1.f / (1.f + expf(-(iz + g_gh[b][oo + H])));
                float n  = tanhf(inn + r * g_gh[b][oo + 2 * H]);
                float hp = g_h[cur][b][oo];
                float hn = (1.f - zz) * n + zz * hp;
                g_h[cur ^ 1][b][oo] = hn;
                if (t == TOUT - 1) d_out[OFF_HT + (size_t)b * H + oo] = hn;
            }
        }
        gen = gsync(gen);

        // ========= Phase C: logits + partial softmax/argmax =========
        if (bid < NPB) {
            int bq = w & 3;            // b = bq + 4j
            int vh = w >> 2;           // v-half
            int vblk = bid * VPB;
            int vbase = vblk + vh * 128;
            const float* hptr = &g_h[cur ^ 1][0][0];

            ull acc[8][4];
            #pragma unroll
            for (int j = 0; j < 8; j++)
                #pragma unroll
                for (int i = 0; i < 4; i++) acc[j][i] = 0ull;

            {
                #pragma unroll
                for (int p = 0; p < 8; p++) {
                    int idx = p * 256 + tid;
                    int vl = idx & 255, kq = idx >> 8;
                    cpa16(sm_u32(&wsm[kq * 256 + vl]),
                          W_out + (size_t)(vblk + vl) * H + 4 * kq);
                }
                int bb = tid >> 3, kq = tid & 7;
                cpa16(sm_u32(&hsm[bb * 8 + kq]), hptr + (size_t)bb * H + 4 * kq);
                asm volatile("cp.async.commit_group;");
            }

            for (int c = 0; c < 16; c++) {
                int buf = c & 1;
                if (c < 15) {
                    int kc = (c + 1) * 32, nb = buf ^ 1;
                    #pragma unroll
                    for (int p = 0; p < 8; p++) {
                        int idx = p * 256 + tid;
                        int vl = idx & 255, kq = idx >> 8;
                        cpa16(sm_u32(&wsm[(size_t)nb * 2048 + kq * 256 + vl]),
                              W_out + (size_t)(vblk + vl) * H + kc + 4 * kq);
                    }
                    int bb = tid >> 3, kq = tid & 7;
                    cpa16(sm_u32(&hsm[(size_t)nb * 256 + bb * 8 + kq]),
                          hptr + (size_t)bb * H + kc + 4 * kq);
                    asm volatile("cp.async.commit_group;");
                    asm volatile("cp.async.wait_group 1;");
                } else {
                    asm volatile("cp.async.wait_group 0;");
                }
                __syncthreads();
                ulonglong2* wstage = wsm + (size_t)buf * 2048;
                ulonglong2* hstage = hsm + (size_t)buf * 256;
                #pragma unroll
                for (int kq = 0; kq < 8; kq++) {
                    ulonglong2 hv[8];
                    #pragma unroll
                    for (int j = 0; j < 8; j++) hv[j] = hstage[(bq + 4 * j) * 8 + kq];
                    #pragma unroll
                    for (int i = 0; i < 4; i++) {
                        ulonglong2 wv = wstage[kq * 256 + vh * 128 + lane + 32 * i];
                        #pragma unroll
                        for (int j = 0; j < 8; j++) {
                            acc[j][i] = fma2(hv[j].x, wv.x, acc[j][i]);
                            acc[j][i] = fma2(hv[j].y, wv.y, acc[j][i]);
                        }
                    }
                }
                __syncthreads();
            }

            float bo[4];
            #pragma unroll
            for (int i = 0; i < 4; i++) bo[i] = b_out[vbase + lane + 32 * i];

            #pragma unroll
            for (int j = 0; j < 8; j++) {
                int b = bq + 4 * j;
                float zv[4];
                float lmax = -INFINITY;
                int lidx = 0;
                #pragma unroll
                for (int i = 0; i < 4; i++) {
                    float lo, hi;
                    upk(acc[j][i], lo, hi);
                    int v = vbase + lane + 32 * i;
                    float z = lo + hi + bo[i];
                    zv[i] = z;
                    __stcs(&g_zbuf[((size_t)t * B + b) * V + v], z);
                    if (z > lmax) { lmax = z; lidx = v; }
                }
                float wm = lmax;
                int wi = lidx;
                #pragma unroll
                for (int off = 16; off; off >>= 1) {
                    float om = __shfl_xor_sync(0xffffffffu, wm, off);
                    int   oi = __shfl_xor_sync(0xffffffffu, wi, off);
                    if (om > wm || (om == wm && oi < wi)) { wm = om; wi = oi; }
                }
                float ls = 0.f;
                #pragma unroll
                for (int i = 0; i < 4; i++) ls += expf(zv[i] - wm);
                #pragma unroll
                for (int off = 16; off; off >>= 1)
                    ls += __shfl_xor_sync(0xffffffffu, ls, off);
                if (lane == 0) {
                    s2m[vh][b] = wm; s2s[vh][b] = ls; s2i[vh][b] = wi;
                }
            }
            __syncthreads();
            if (tid < B) {
                int b = tid;
                float m0 = s2m[0][b], m1 = s2m[1][b];
                float M = fmaxf(m0, m1);
                float S = s2s[0][b] * expf(m0 - M) + s2s[1][b] * expf(m1 - M);
                int I = (m0 >= m1) ? s2i[0][b] : s2i[1][b];  // ties -> lower v
                g_pmax[bid][b] = M;
                g_psum[bid][b] = S;
                g_pidx[bid][b] = I;
            }
        }
        gen = gsync(gen);
        cur ^= 1;
    }

    // ---------------- final logZ[TOUT-1] (block 0) ----------------
    if (bid == 0) {
        int b = lane, part = w;
        float m = -INFINITY, s = 0.f;
        for (int i = part; i < NPB; i += 8) {
            float pm = g_pmax[i][b], ps = g_psum[i][b];
            if (pm > m) { s = s * expf(m - pm) + ps; m = pm; }
            else        { s += ps * expf(pm - m); }
        }
        sm_m[part][b] = m; sm_s[part][b] = s;
        __syncthreads();
        if (tid < B) {
            float M = -INFINITY, S = 0.f;
            #pragma unroll
            for (int p = 0; p < 8; p++) {
                float pm = sm_m[p][tid], ps = sm_s[p][tid];
                if (pm > M) { S = S * expf(M - pm) + ps; M = pm; }
                else        { S += ps * expf(pm - M); }
            }
            g_logZ[TOUT - 1][tid] = M + logf(S);
        }
    }
}

// ============================================================================
// E2: out[b][v][t] = z[t][b][v] - logZ[t][b]   (smem-tiled transpose)
// ============================================================================
extern "C" __global__ void __launch_bounds__(256)
e2_kernel(float* __restrict__ d_out) {
    __shared__ float s_z[128][52];
    __shared__ float s_lz[TOUT];
    int b = blockIdx.y;
    int v0 = blockIdx.x * 128;
    int tid = threadIdx.x;
    if (tid < TOUT) s_lz[tid] = g_logZ[tid][b];
    __syncthreads();
    for (int j = tid; j < 128 * TOUT; j += 256) {
        int tt = j >> 7, vl = j & 127;
        s_z[vl][tt] = g_zbuf[((size_t)tt * B + b) * V + v0 + vl] - s_lz[tt];
    }
    __syncthreads();
    size_t base = ((size_t)b * V + v0) * TOUT;
    for (int j = tid; j < 128 * TOUT; j += 256) {
        int vl = j / TOUT, tt = j % TOUT;
        d_out[base + j] = s_z[vl][tt];
    }
}

// ============================================================================
extern "C" void kernel_launch(void* const* d_in, const int* in_sizes, int n_in,
                              void* d_out_v, int out_size) {
    const float* enc    = (const float*)d_in[0];
    const int*   y      = (const int*)d_in[1];
    const float* emb    = (const float*)d_in[2];
    // d_in[3..6]: W_fc, b_fc, W_fc1, W_fc2 — dead (softmax over singleton axis)
    const float* W_comb = (const float*)d_in[7];
    const float* b_comb = (const float*)d_in[8];
    const float* W_ih   = (const float*)d_in[9];
    const float* W_hh   = (const float*)d_in[10];
    const float* b_ih   = (const float*)d_in[11];
    const float* b_hh   = (const float*)d_in[12];
    const float* W_out  = (const float*)d_in[13];
    const float* b_out  = (const float*)d_in[14];
    float* d_out = (float*)d_out_v;

    const int main_smem = 65792 + 16384;   // 82176 (covers C's 73728 too)
    cudaFuncSetAttribute(main_kernel, cudaFuncAttributeMaxDynamicSharedMemorySize,
                         main_smem);

    p1_kernel<<<512, 256>>>(enc, y, d_out);
    main_kernel<<<GRID, 256, main_smem>>>(emb, W_comb, b_comb, W_hh, b_hh,
                                          W_ih, b_ih, W_out, b_out, d_out);
    e2_kernel<<<dim3(V / 128, B), 256>>>(d_out);
}

// round 11
// speedup vs baseline: 5.0012x; 1.6162x over previous
#include <cuda_runtime.h>
#include <cuda_bf16.h>
#include <math.h>
#include <stdint.h>
#include <string.h>
#include <limits.h>

#define B    32
#define H    512
#define V    32000
#define TIN  50
#define TOUT 50
#define GRID 128      // persistent blocks (1/SM, all co-resident)
#define NPB  125      // projection blocks (V / VPB)
#define VPB  256      // v-columns per projection block
#define NVT  (V / 16) // 2000 v-tiles
#define NKT  (H / 16) // 32 k-tiles

#define OFF_HT   ((size_t)B * V * TOUT)          // 51,200,000
#define OFF_ATTN (OFF_HT + (size_t)B * H)        // 51,216,384

typedef unsigned long long ull;

// ---------------- device scratch (static, allowed) ----------------
__device__ float g_zbuf[(size_t)TOUT * B * V];   // raw logits, 204.8 MB
__device__ uint4 g_w1f[(size_t)NVT * NKT * 32];  // W_out bf16-hi frags, 32.8 MB
__device__ uint4 g_w2f[(size_t)NVT * NKT * 32];  // W_out bf16-lo frags, 32.8 MB
__device__ unsigned g_hpk[H * B];                // packed (h1,h2) [k][b]
__device__ float g_pmax[NPB][B];
__device__ float g_psum[NPB][B];
__device__ int   g_pidx[NPB][B];
__device__ float g_logZ[TOUT][B];
__device__ float g_h[2][B][H];
__device__ float g_xc[B][H];
__device__ float g_gh[B][3 * H];
__device__ float g_attnx[B][H];
__device__ float g_cattn[B][H];
__device__ int   g_tok[B];
__device__ unsigned g_bar_cnt;                   // monotonic
__device__ unsigned g_bar_gen;                   // monotonic

// ---------------- helpers ----------------
__device__ __forceinline__ ull fma2(ull a, ull b, ull c) {
    ull d;
    asm("fma.rn.f32x2 %0, %1, %2, %3;" : "=l"(d) : "l"(a), "l"(b), "l"(c));
    return d;
}
__device__ __forceinline__ float sum2(ull v) {
    float lo, hi;
    asm("mov.b64 {%0, %1}, %2;" : "=f"(lo), "=f"(hi) : "l"(v));
    return lo + hi;
}
__device__ __forceinline__ unsigned sm_u32(const void* p) {
    return (unsigned)__cvta_generic_to_shared(p);
}
__device__ __forceinline__ void cpa16(unsigned d, const void* s) {
    asm volatile("cp.async.cg.shared.global [%0], [%1], 16;" :: "r"(d), "l"(s));
}
__device__ __forceinline__ unsigned prmt(unsigned a, unsigned b, unsigned sel) {
    unsigned d;
    asm("prmt.b32 %0, %1, %2, %3;" : "=r"(d) : "r"(a), "r"(b), "r"(sel));
    return d;
}
__device__ __forceinline__ void mma16816(float* d, const uint4& a,
                                         unsigned b0, unsigned b1) {
    asm volatile(
        "mma.sync.aligned.m16n8k16.row.col.f32.bf16.bf16.f32 "
        "{%0,%1,%2,%3}, {%4,%5,%6,%7}, {%8,%9}, {%0,%1,%2,%3};"
        : "+f"(d[0]), "+f"(d[1]), "+f"(d[2]), "+f"(d[3])
        : "r"(a.x), "r"(a.y), "r"(a.z), "r"(a.w), "r"(b0), "r"(b1));
}
// split x -> bf16 hi (o1 halves) and bf16 residual (o2 halves); pair packs (x lo, y hi)
__device__ __forceinline__ void cvt2(float2 v, unsigned& o1, unsigned& o2) {
    __nv_bfloat16 ax = __float2bfloat16_rn(v.x), ay = __float2bfloat16_rn(v.y);
    float rx = v.x - __bfloat162float(ax), ry = v.y - __bfloat162float(ay);
    __nv_bfloat16 bx = __float2bfloat16_rn(rx), by = __float2bfloat16_rn(ry);
    unsigned short uax, uay, ubx, uby;
    memcpy(&uax, &ax, 2); memcpy(&uay, &ay, 2);
    memcpy(&ubx, &bx, 2); memcpy(&uby, &by, 2);
    o1 = ((unsigned)uay << 16) | uax;
    o2 = ((unsigned)uby << 16) | ubx;
}
__device__ __forceinline__ unsigned pack_h(float x) {
    __nv_bfloat16 h1 = __float2bfloat16_rn(x);
    float r = x - __bfloat162float(h1);
    __nv_bfloat16 h2 = __float2bfloat16_rn(r);
    unsigned short u1, u2;
    memcpy(&u1, &h1, 2); memcpy(&u2, &h2, 2);
    return ((unsigned)u2 << 16) | u1;
}

// Device-wide barrier: monotonic release/acquire (all GRID blocks co-resident).
__device__ __forceinline__ unsigned gsync(unsigned gen) {
    __syncthreads();
    if (threadIdx.x == 0) {
        unsigned next = gen + 1u;
        unsigned old;
        asm volatile("atom.release.gpu.global.add.u32 %0, [%1], %2;"
                     : "=r"(old) : "l"(&g_bar_cnt), "r"(1u) : "memory");
        if (old == next * GRID - 1u) {
            asm volatile("st.release.gpu.global.u32 [%0], %1;"
                         :: "l"(&g_bar_gen), "r"(next) : "memory");
        } else {
            unsigned cur;
            do {
                __nanosleep(32);
                asm volatile("ld.acquire.gpu.global.u32 %0, [%1];"
                             : "=r"(cur) : "l"(&g_bar_gen) : "memory");
            } while ((int)(cur - next) < 0);
        }
    }
    __syncthreads();
    return gen + 1u;
}

// ============================================================================
// P0: convert W_out -> fragment-ordered bf16 split arrays (once)
//   frag = vt*NKT + kt ; per lane a0..a3 per m16n8k16 A-layout (row-major W)
// ============================================================================
extern "C" __global__ void __launch_bounds__(256)
p0_kernel(const float* __restrict__ W_out) {
    size_t gid = (size_t)blockIdx.x * 256 + threadIdx.x;   // < NVT*NKT*32
    int lane = (int)(gid & 31);
    size_t frag = gid >> 5;
    int kt = (int)(frag & (NKT - 1));
    size_t vt = frag >> 5;
    int g = lane >> 2, tg = lane & 3;
    size_t v0 = vt * 16 + g;
    int k0 = kt * 16 + tg * 2;
    const float* p00 = W_out + v0 * H + k0;
    float2 w00 = *reinterpret_cast<const float2*>(p00);            // a0
    float2 w01 = *reinterpret_cast<const float2*>(p00 + 8);        // a2
    float2 w10 = *reinterpret_cast<const float2*>(p00 + 8 * H);    // a1
    float2 w11 = *reinterpret_cast<const float2*>(p00 + 8 * H + 8);// a3
    uint4 f1, f2;
    cvt2(w00, f1.x, f2.x);
    cvt2(w10, f1.y, f2.y);
    cvt2(w01, f1.z, f2.z);
    cvt2(w11, f1.w, f2.w);
    g_w1f[frag * 32 + lane] = f1;
    g_w2f[frag * 32 + lane] = f2;
}

// ============================================================================
// P1: attn_x = sum_t encoder_out ; h0 = 0 ; attn output = ones ; tok0
// ============================================================================
extern "C" __global__ void p1_kernel(const float* __restrict__ enc,
                                     const int* __restrict__ y,
                                     float* __restrict__ d_out) {
    int gid  = blockIdx.x * blockDim.x + threadIdx.x;
    int nthr = gridDim.x * blockDim.x;
    if (gid < B) g_tok[gid] = y[gid * TOUT];     // y[b][0]
    for (int i = gid; i < B * H; i += nthr) {
        int b = i >> 9, k = i & 511;
        g_h[0][b][k] = 0.f;
        float s = 0.f;
        #pragma unroll 5
        for (int tt = 0; tt < TIN; tt++) s += enc[((size_t)b * TIN + tt) * H + k];
        g_attnx[b][k] = s;
    }
    float4 one4 = make_float4(1.f, 1.f, 1.f, 1.f);
    float4* dst = reinterpret_cast<float4*>(d_out + OFF_ATTN);
    size_t n4 = (size_t)TOUT * B * TIN * H / 4;
    for (size_t i = gid; i < n4; i += nthr) dst[i] = one4;
}

// ============================================================================
// MAIN persistent kernel
//   smem union:
//     A/B/prologue: inp pairs [32][257] (65792 B) + wtile[2][16][64] (16384 B)
//     C:            Pw [512][36] u32 (73728 B) + ztile [256][33] f32 (33792 B)
// ============================================================================
#define S_PAD 257
extern "C" __global__ void __launch_bounds__(256, 1)
main_kernel(const float* __restrict__ emb,
            const float* __restrict__ W_comb, const float* __restrict__ b_comb,
            const float* __restrict__ W_hh,  const float* __restrict__ b_hh,
            const float* __restrict__ W_ih,  const float* __restrict__ b_ih,
            const float* __restrict__ b_out, float* __restrict__ d_out) {
    extern __shared__ char dsm[];
    ull* inp = reinterpret_cast<ull*>(dsm);                       // [32][S_PAD]
    ull* wtile = reinterpret_cast<ull*>(dsm + 65792);             // [2][16][64]
    unsigned* Pw = reinterpret_cast<unsigned*>(dsm);              // C: [512][36]
    float* zt = reinterpret_cast<float*>(dsm + 73728);            // C: [256][33]

    __shared__ int   s_tok[B];
    __shared__ float sm_m[8][B], sm_s[8][B], sm_av[8][B];
    __shared__ int   sm_ai[8][B];
    __shared__ float sp[12][33];

    int tid = threadIdx.x, bid = blockIdx.x;
    int lane = tid & 31, w = tid >> 5;
    int g = lane >> 2, tg = lane & 3;
    unsigned gen;
    asm volatile("ld.acquire.gpu.global.u32 %0, [%1];" : "=r"(gen) : "l"(&g_bar_gen));

    // ============== prologue: c_attn (blocks 0..31, A-style) ==============
    if (bid < 32) {
        int row0 = bid * 16;
        const float* wbase = W_comb + H;       // attn-half of W_comb rows
        const size_t wstride = 2 * H;
        #pragma unroll
        for (int cc = 0; cc < 2; cc++) {
            #pragma unroll
            for (int p = 0; p < 2; p++) {
                int idx = p * 256 + tid;
                int r = idx >> 5, jj = idx & 31;
                cpa16(sm_u32(&wtile[(size_t)cc * 1024 + r * 64 + jj * 2]),
                      wbase + (size_t)(row0 + r) * wstride + cc * 128 + jj * 4);
            }
            asm volatile("cp.async.commit_group;");
        }
        for (int i = tid; i < B * 256; i += 256) {
            int b = i >> 8, kq = i & 255;
            float2 v = *reinterpret_cast<const float2*>(&g_attnx[b][2 * kq]);
            *reinterpret_cast<float2*>(&inp[b * S_PAD + kq]) = v;
        }
        ull a00 = 0, a01 = 0, a10 = 0, a11 = 0;
        for (int c = 0; c < 4; c++) {
            if (c < 3) asm volatile("cp.async.wait_group 1;");
            else       asm volatile("cp.async.wait_group 0;");
            __syncthreads();
            const ull* wch = wtile + (size_t)(c & 1) * 1024;
            int r0 = (2 * w) * 64, r1 = (2 * w + 1) * 64;
            const ull* xrow = inp + lane * S_PAD + c * 64;
            #pragma unroll 8
            for (int q = 0; q < 64; q += 2) {
                ull x0 = xrow[q], x1 = xrow[q + 1];
                a00 = fma2(wch[r0 + q], x0, a00);
                a01 = fma2(wch[r0 + q + 1], x1, a01);
                a10 = fma2(wch[r1 + q], x0, a10);
                a11 = fma2(wch[r1 + q + 1], x1, a11);
            }
            __syncthreads();
            if (c < 2) {
                #pragma unroll
                for (int p = 0; p < 2; p++) {
                    int idx = p * 256 + tid;
                    int r = idx >> 5, jj = idx & 31;
                    cpa16(sm_u32(&wtile[(size_t)(c & 1) * 1024 + r * 64 + jj * 2]),
                          wbase + (size_t)(row0 + r) * wstride + (c + 2) * 128 + jj * 4);
                }
                asm volatile("cp.async.commit_group;");
            }
        }
        int o0 = row0 + 2 * w;
        g_cattn[lane][o0]     = sum2(a00) + sum2(a01) + b_comb[o0];
        g_cattn[lane][o0 + 1] = sum2(a10) + sum2(a11) + b_comb[o0 + 1];
    }
    gen = gsync(gen);

    int cur = 0;
    for (int t = 0; t < TOUT; t++) {
        // ========= Phase A: (xc blocks: merge->tok) + xc / gh GEMMs =========
        {
            bool is_xc = (bid < 32);
            int row0;
            const float* wbase;
            size_t wstride;
            if (is_xc) { row0 = bid * 16; wbase = W_comb; wstride = 2 * H; }
            else       { row0 = (bid - 32) * 16; wbase = W_hh; wstride = H; }

            #pragma unroll
            for (int cc = 0; cc < 2; cc++) {
                #pragma unroll
                for (int p = 0; p < 2; p++) {
                    int idx = p * 256 + tid;
                    int r = idx >> 5, jj = idx & 31;
                    cpa16(sm_u32(&wtile[(size_t)cc * 1024 + r * 64 + jj * 2]),
                          wbase + (size_t)(row0 + r) * wstride + cc * 128 + jj * 4);
                }
                asm volatile("cp.async.commit_group;");
            }

            if (is_xc) {
                if (t > 0) {
                    int b = lane, part = w;
                    float m = -INFINITY, s = 0.f, av = -INFINITY;
                    int ai = INT_MAX;
                    for (int i = part; i < NPB; i += 8) {
                        float pm = g_pmax[i][b];
                        float ps = g_psum[i][b];
                        int   pi = g_pidx[i][b];
                        if (pm > m) { s = s * expf(m - pm) + ps; m = pm; }
                        else        { s += ps * expf(pm - m); }
                        if (pm > av || (pm == av && pi < ai)) { av = pm; ai = pi; }
                    }
                    sm_m[part][b] = m; sm_s[part][b] = s;
                    sm_av[part][b] = av; sm_ai[part][b] = ai;
                    __syncthreads();
                    if (tid < B) {
                        float M = -INFINITY, S = 0.f, AV = -INFINITY;
                        int AI = INT_MAX;
                        #pragma unroll
                        for (int p = 0; p < 8; p++) {
                            float pm = sm_m[p][tid], ps = sm_s[p][tid];
                            if (pm > M) { S = S * expf(M - pm) + ps; M = pm; }
                            else        { S += ps * expf(pm - M); }
                            float v2 = sm_av[p][tid]; int i2 = sm_ai[p][tid];
                            if (v2 > AV || (v2 == AV && i2 < AI)) { AV = v2; AI = i2; }
                        }
                        s_tok[tid] = AI;
                        if (bid == 0) g_logZ[t - 1][tid] = M + logf(S);
                    }
                } else {
                    if (tid < B) s_tok[tid] = g_tok[tid];
                }
                __syncthreads();
            }

            for (int i = tid; i < B * 256; i += 256) {
                int b = i >> 8, kq = i & 255;
                const float* src = is_xc ? (emb + (size_t)s_tok[b] * H)
                                         : &g_h[cur][b][0];
                float2 v = *reinterpret_cast<const float2*>(src + 2 * kq);
                *reinterpret_cast<float2*>(&inp[b * S_PAD + kq]) = v;
            }

            ull a00 = 0, a01 = 0, a10 = 0, a11 = 0;
            for (int c = 0; c < 4; c++) {
                if (c < 3) asm volatile("cp.async.wait_group 1;");
                else       asm volatile("cp.async.wait_group 0;");
                __syncthreads();
                const ull* wch = wtile + (size_t)(c & 1) * 1024;
                int r0 = (2 * w) * 64, r1 = (2 * w + 1) * 64;
                const ull* xrow = inp + lane * S_PAD + c * 64;
                #pragma unroll 8
                for (int q = 0; q < 64; q += 2) {
                    ull x0 = xrow[q], x1 = xrow[q + 1];
                    a00 = fma2(wch[r0 + q], x0, a00);
                    a01 = fma2(wch[r0 + q + 1], x1, a01);
                    a10 = fma2(wch[r1 + q], x0, a10);
                    a11 = fma2(wch[r1 + q + 1], x1, a11);
                }
                __syncthreads();
                if (c < 2) {
                    #pragma unroll
                    for (int p = 0; p < 2; p++) {
                        int idx = p * 256 + tid;
                        int r = idx >> 5, jj = idx & 31;
                        cpa16(sm_u32(&wtile[(size_t)(c & 1) * 1024 + r * 64 + jj * 2]),
                              wbase + (size_t)(row0 + r) * wstride + (c + 2) * 128 + jj * 4);
                    }
                    asm volatile("cp.async.commit_group;");
                }
            }
            float v0 = sum2(a00) + sum2(a01);
            float v1 = sum2(a10) + sum2(a11);
            int o0 = row0 + 2 * w, o1 = o0 + 1;
            if (is_xc) {
                v0 += g_cattn[lane][o0];
                v1 += g_cattn[lane][o1];
                g_xc[lane][o0] = v0 > 0.f ? v0 : 0.f;
                g_xc[lane][o1] = v1 > 0.f ? v1 : 0.f;
            } else {
                g_gh[lane][o0] = v0 + b_hh[o0];
                g_gh[lane][o1] = v1 + b_hh[o1];
            }
        }
        gen = gsync(gen);

        // ========= Phase B: gi (12 rows/block) + GRU + pack h =========
        {
            int obase = bid * 4;
            #pragma unroll
            for (int cc = 0; cc < 2; cc++) {
                #pragma unroll
                for (int p = 0; p < 2; p++) {
                    int idx = p * 256 + tid;
                    if (idx < 384) {
                        int r = idx >> 5, jj = idx & 31;
                        int gg = r >> 2, ol = r & 3;
                        cpa16(sm_u32(&wtile[(size_t)cc * 1024 + r * 64 + jj * 2]),
                              W_ih + (size_t)(gg * H + obase + ol) * H + cc * 128 + jj * 4);
                    }
                }
                asm volatile("cp.async.commit_group;");
            }
            for (int i = tid; i < B * 256; i += 256) {
                int b = i >> 8, kq = i & 255;
                float2 v = *reinterpret_cast<const float2*>(&g_xc[b][2 * kq]);
                *reinterpret_cast<float2*>(&inp[b * S_PAD + kq]) = v;
            }
            ull a00 = 0, a01 = 0, a10 = 0, a11 = 0;
            for (int c = 0; c < 4; c++) {
                if (c < 3) asm volatile("cp.async.wait_group 1;");
                else       asm volatile("cp.async.wait_group 0;");
                __syncthreads();
                if (w < 6) {
                    const ull* wch = wtile + (size_t)(c & 1) * 1024;
                    int r0 = (2 * w) * 64, r1 = (2 * w + 1) * 64;
                    const ull* xrow = inp + lane * S_PAD + c * 64;
                    #pragma unroll 8
                    for (int q = 0; q < 64; q += 2) {
                        ull x0 = xrow[q], x1 = xrow[q + 1];
                        a00 = fma2(wch[r0 + q], x0, a00);
                        a01 = fma2(wch[r0 + q + 1], x1, a01);
                        a10 = fma2(wch[r1 + q], x0, a10);
                        a11 = fma2(wch[r1 + q + 1], x1, a11);
                    }
                }
                __syncthreads();
                if (c < 2) {
                    #pragma unroll
                    for (int p = 0; p < 2; p++) {
                        int idx = p * 256 + tid;
                        if (idx < 384) {
                            int r = idx >> 5, jj = idx & 31;
                            int gg = r >> 2, ol = r & 3;
                            cpa16(sm_u32(&wtile[(size_t)(c & 1) * 1024 + r * 64 + jj * 2]),
                                  W_ih + (size_t)(gg * H + obase + ol) * H + (c + 2) * 128 + jj * 4);
                        }
                    }
                    asm volatile("cp.async.commit_group;");
                }
            }
            if (w < 6) {
                sp[2 * w][lane]     = sum2(a00) + sum2(a01);
                sp[2 * w + 1][lane] = sum2(a10) + sum2(a11);
            }
            __syncthreads();
            if (tid < 128) {
                int b = tid & 31, ol = tid >> 5;
                int oo = obase + ol;
                float ir  = sp[ol][b]     + b_ih[oo];
                float iz  = sp[4 + ol][b] + b_ih[oo + H];
                float inn = sp[8 + ol][b] + b_ih[oo + 2 * H];
                float r  = 1.f / (1.f + expf(-(ir + g_gh[b][oo])));
                float zz = 1.f / (1.f + expf(-(iz + g_gh[b][oo + H])));
                float n  = tanhf(inn + r * g_gh[b][oo + 2 * H]);
                float hp = g_h[cur][b][oo];
                float hn = (1.f - zz) * n + zz * hp;
                g_h[cur ^ 1][b][oo] = hn;
                g_hpk[oo * 32 + b] = pack_h(hn);
                if (t == TOUT - 1) d_out[OFF_HT + (size_t)b * H + oo] = hn;
            }
        }
        gen = gsync(gen);

        // ========= Phase C: z = h @ W_out^T + b_out via bf16x3 mma.sync =====
        if (bid < NPB) {
            // stage packed h: Pw[k][36] = g_hpk[k][b]
            for (int i = tid; i < 4096; i += 256) {
                int k = i >> 3, b4 = (i & 7) * 4;
                uint4 v = *reinterpret_cast<const uint4*>(&g_hpk[k * 32 + b4]);
                *reinterpret_cast<uint4*>(&Pw[k * 36 + b4]) = v;
            }
            __syncthreads();

            size_t gvt0 = (size_t)bid * 16 + 2 * w;   // warp's first v-tile
            const uint4* W1p = g_w1f + gvt0 * NKT * 32 + lane;
            const uint4* W2p = g_w2f + gvt0 * NKT * 32 + lane;
            float acc[2][4][4];
            #pragma unroll
            for (int a = 0; a < 2; a++)
                #pragma unroll
                for (int bb = 0; bb < 4; bb++)
                    #pragma unroll
                    for (int cc = 0; cc < 4; cc++) acc[a][bb][cc] = 0.f;

            uint4 a1c[2], a2c[2];
            a1c[0] = __ldg(W1p);             a1c[1] = __ldg(W1p + NKT * 32);
            a2c[0] = __ldg(W2p);             a2c[1] = __ldg(W2p + NKT * 32);

            for (int kt = 0; kt < NKT; kt++) {
                uint4 a1n[2], a2n[2];
                if (kt < NKT - 1) {
                    a1n[0] = __ldg(W1p + (kt + 1) * 32);
                    a1n[1] = __ldg(W1p + NKT * 32 + (kt + 1) * 32);
                    a2n[0] = __ldg(W2p + (kt + 1) * 32);
                    a2n[1] = __ldg(W2p + NKT * 32 + (kt + 1) * 32);
                }
                unsigned bf1[4][2], bf2[4][2];
                #pragma unroll
                for (int bt = 0; bt < 4; bt++) {
                    int n = bt * 8 + g;
                    #pragma unroll
                    for (int r = 0; r < 2; r++) {
                        int k0 = kt * 16 + tg * 2 + r * 8;
                        unsigned e0 = Pw[k0 * 36 + n];
                        unsigned e1 = Pw[(k0 + 1) * 36 + n];
                        bf1[bt][r] = prmt(e0, e1, 0x5410u);
                        bf2[bt][r] = prmt(e0, e1, 0x7632u);
                    }
                }
                #pragma unroll
                for (int vtl = 0; vtl < 2; vtl++)
                    #pragma unroll
                    for (int bt = 0; bt < 4; bt++) {
                        mma16816(acc[vtl][bt], a1c[vtl], bf1[bt][0], bf1[bt][1]);
                        mma16816(acc[vtl][bt], a1c[vtl], bf2[bt][0], bf2[bt][1]);
                        mma16816(acc[vtl][bt], a2c[vtl], bf1[bt][0], bf1[bt][1]);
                    }
                if (kt < NKT - 1) {
                    a1c[0] = a1n[0]; a1c[1] = a1n[1];
                    a2c[0] = a2n[0]; a2c[1] = a2n[1];
                }
            }

            int vbase = bid * VPB;
            #pragma unroll
            for (int vtl = 0; vtl < 2; vtl++) {
                int lv0 = (2 * w + vtl) * 16 + g;
                float bi0 = b_out[vbase + lv0];
                float bi8 = b_out[vbase + lv0 + 8];
                #pragma unroll
                for (int bt = 0; bt < 4; bt++) {
                    int bb = bt * 8 + tg * 2;
                    zt[lv0 * 33 + bb]           = acc[vtl][bt][0] + bi0;
                    zt[lv0 * 33 + bb + 1]       = acc[vtl][bt][1] + bi0;
                    zt[(lv0 + 8) * 33 + bb]     = acc[vtl][bt][2] + bi8;
                    zt[(lv0 + 8) * 33 + bb + 1] = acc[vtl][bt][3] + bi8;
                }
            }
            __syncthreads();

            // per-(b,seg) partials: warp spans b (conflict-free column reads)
            {
                int b = tid & 31, seg = tid >> 5;
                float m = -INFINITY;
                int mi = 0;
                #pragma unroll 8
                for (int i = 0; i < 32; i++) {
                    int lv = seg * 32 + i;
                    float z = zt[lv * 33 + b];
                    if (z > m) { m = z; mi = vbase + lv; }
                }
                float s = 0.f;
                #pragma unroll 8
                for (int i = 0; i < 32; i++) {
                    int lv = seg * 32 + i;
                    s += expf(zt[lv * 33 + b] - m);
                }
                sm_m[seg][b] = m; sm_s[seg][b] = s; sm_ai[seg][b] = mi;
            }
            // coalesced v-major zbuf writeout
            for (int j = tid; j < B * VPB; j += 256) {
                int b = j >> 8, lv = j & 255;
                __stcs(&g_zbuf[((size_t)t * B + b) * V + vbase + lv],
                       zt[lv * 33 + b]);
            }
            __syncthreads();
            if (tid < B) {
                int b = tid;
                float M = -INFINITY, S = 0.f;
                int I = INT_MAX;
                #pragma unroll
                for (int p = 0; p < 8; p++) {
                    float pm = sm_m[p][b], ps = sm_s[p][b];
                    if (pm > M) { S = S * expf(M - pm) + ps; M = pm; I = sm_ai[p][b]; }
                    else        { S += ps * expf(pm - M); }
                }
                g_pmax[bid][b] = M;
                g_psum[bid][b] = S;
                g_pidx[bid][b] = I;
            }
        }
        gen = gsync(gen);
        cur ^= 1;
    }

    // ---------------- final logZ[TOUT-1] (block 0) ----------------
    if (bid == 0) {
        int b = lane, part = w;
        float m = -INFINITY, s = 0.f;
        for (int i = part; i < NPB; i += 8) {
            float pm = g_pmax[i][b], ps = g_psum[i][b];
            if (pm > m) { s = s * expf(m - pm) + ps; m = pm; }
            else        { s += ps * expf(pm - m); }
        }
        sm_m[part][b] = m; sm_s[part][b] = s;
        __syncthreads();
        if (tid < B) {
            float M = -INFINITY, S = 0.f;
            #pragma unroll
            for (int p = 0; p < 8; p++) {
                float pm = sm_m[p][tid], ps = sm_s[p][tid];
                if (pm > M) { S = S * expf(M - pm) + ps; M = pm; }
                else        { S += ps * expf(pm - M); }
            }
            g_logZ[TOUT - 1][tid] = M + logf(S);
        }
    }
}

// ============================================================================
// E2: out[b][v][t] = z[t][b][v] - logZ[t][b]   (smem-tiled transpose)
// ============================================================================
extern "C" __global__ void __launch_bounds__(256)
e2_kernel(float* __restrict__ d_out) {
    __shared__ float s_z[128][52];
    __shared__ float s_lz[TOUT];
    int b = blockIdx.y;
    int v0 = blockIdx.x * 128;
    int tid = threadIdx.x;
    if (tid < TOUT) s_lz[tid] = g_logZ[tid][b];
    __syncthreads();
    for (int j = tid; j < 128 * TOUT; j += 256) {
        int tt = j >> 7, vl = j & 127;
        s_z[vl][tt] = g_zbuf[((size_t)tt * B + b) * V + v0 + vl] - s_lz[tt];
    }
    __syncthreads();
    size_t base = ((size_t)b * V + v0) * TOUT;
    for (int j = tid; j < 128 * TOUT; j += 256) {
        int vl = j / TOUT, tt = j % TOUT;
        d_out[base + j] = s_z[vl][tt];
    }
}

// ============================================================================
extern "C" void kernel_launch(void* const* d_in, const int* in_sizes, int n_in,
                              void* d_out_v, int out_size) {
    const float* enc    = (const float*)d_in[0];
    const int*   y      = (const int*)d_in[1];
    const float* emb    = (const float*)d_in[2];
    // d_in[3..6]: W_fc, b_fc, W_fc1, W_fc2 — dead (softmax over singleton axis)
    const float* W_comb = (const float*)d_in[7];
    const float* b_comb = (const float*)d_in[8];
    const float* W_ih   = (const float*)d_in[9];
    const float* W_hh   = (const float*)d_in[10];
    const float* b_ih   = (const float*)d_in[11];
    const float* b_hh   = (const float*)d_in[12];
    const float* W_out  = (const float*)d_in[13];
    const float* b_out  = (const float*)d_in[14];
    float* d_out = (float*)d_out_v;

    const int main_smem = 73728 + 256 * 33 * 4;    // 107520 (covers A/B's 82176)
    cudaFuncSetAttribute(main_kernel, cudaFuncAttributeMaxDynamicSharedMemorySize,
                         main_smem);

    p0_kernel<<<(NVT * NKT * 32) / 256, 256>>>(W_out);
    p1_kernel<<<512, 256>>>(enc, y, d_out);
    main_kernel<<<GRID, 256, main_smem>>>(emb, W_comb, b_comb, W_hh, b_hh,
                                          W_ih, b_ih, b_out, d_out);
    e2_kernel<<<dim3(V / 128, B), 256>>>(d_out);
}

// round 14
// speedup vs baseline: 5.0121x; 1.0022x over previous
#include <cuda_runtime.h>
#include <cuda_bf16.h>
#include <math.h>
#include <stdint.h>
#include <string.h>
#include <limits.h>

#define B    32
#define H    512
#define V    32000
#define TIN  50
#define TOUT 50
#define GRID 128      // persistent blocks (1/SM, all co-resident)
#define NPB  125      // projection blocks (V / VPB)
#define VPB  256      // v-columns per projection block
#define NVT  (V / 16) // 2000 v-tiles
#define NKT  (H / 16) // 32 k-tiles

#define OFF_HT   ((size_t)B * V * TOUT)          // 51,200,000
#define OFF_ATTN (OFF_HT + (size_t)B * H)        // 51,216,384

typedef unsigned long long ull;

// ---------------- device scratch (static, allowed) ----------------
__device__ float g_zbuf[(size_t)TOUT * B * V];   // raw logits, 204.8 MB
__device__ uint4 g_w1f[(size_t)NVT * NKT * 32];  // W_out bf16-hi frags, 32.8 MB
__device__ uint4 g_w2f[(size_t)NVT * NKT * 32];  // W_out bf16-lo frags, 32.8 MB
__device__ unsigned g_hpk[H * B];                // packed (h1,h2) [k][b]
__device__ float g_pmax[NPB][B];
__device__ float g_psum[NPB][B];
__device__ int   g_pidx[NPB][B];
__device__ float g_logZ[TOUT][B];
__device__ float g_h[2][B][H];
__device__ float g_xc[B][H];
__device__ float g_gh[B][3 * H];
__device__ float g_attnx[B][H];
__device__ float g_cattn[B][H];
__device__ int   g_tok[B];
__device__ unsigned g_bar_cnt;                   // monotonic
__device__ unsigned g_bar_gen;                   // monotonic

// ---------------- helpers ----------------
__device__ __forceinline__ ull fma2(ull a, ull b, ull c) {
    ull d;
    asm("fma.rn.f32x2 %0, %1, %2, %3;" : "=l"(d) : "l"(a), "l"(b), "l"(c));
    return d;
}
__device__ __forceinline__ float sum2(ull v) {
    float lo, hi;
    asm("mov.b64 {%0, %1}, %2;" : "=f"(lo), "=f"(hi) : "l"(v));
    return lo + hi;
}
__device__ __forceinline__ unsigned sm_u32(const void* p) {
    return (unsigned)__cvta_generic_to_shared(p);
}
__device__ __forceinline__ void cpa16(unsigned d, const void* s) {
    asm volatile("cp.async.cg.shared.global [%0], [%1], 16;" :: "r"(d), "l"(s));
}
__device__ __forceinline__ unsigned prmt(unsigned a, unsigned b, unsigned sel) {
    unsigned d;
    asm("prmt.b32 %0, %1, %2, %3;" : "=r"(d) : "r"(a), "r"(b), "r"(sel));
    return d;
}
__device__ __forceinline__ void mma16816(float* d, const uint4& a,
                                         unsigned b0, unsigned b1) {
    asm volatile(
        "mma.sync.aligned.m16n8k16.row.col.f32.bf16.bf16.f32 "
        "{%0,%1,%2,%3}, {%4,%5,%6,%7}, {%8,%9}, {%0,%1,%2,%3};"
        : "+f"(d[0]), "+f"(d[1]), "+f"(d[2]), "+f"(d[3])
        : "r"(a.x), "r"(a.y), "r"(a.z), "r"(a.w), "r"(b0), "r"(b1));
}
// split float2 -> bf16-hi pair word and bf16-residual pair word
__device__ __forceinline__ void cvt2(float2 v, unsigned& o1, unsigned& o2) {
    __nv_bfloat16 ax = __float2bfloat16_rn(v.x), ay = __float2bfloat16_rn(v.y);
    float rx = v.x - __bfloat162float(ax), ry = v.y - __bfloat162float(ay);
    __nv_bfloat16 bx = __float2bfloat16_rn(rx), by = __float2bfloat16_rn(ry);
    unsigned short uax, uay, ubx, uby;
    memcpy(&uax, &ax, 2); memcpy(&uay, &ay, 2);
    memcpy(&ubx, &bx, 2); memcpy(&uby, &by, 2);
    o1 = ((unsigned)uay << 16) | uax;
    o2 = ((unsigned)uby << 16) | ubx;
}
__device__ __forceinline__ unsigned pack_h(float x) {
    __nv_bfloat16 h1 = __float2bfloat16_rn(x);
    float r = x - __bfloat162float(h1);
    __nv_bfloat16 h2 = __float2bfloat16_rn(r);
    unsigned short u1, u2;
    memcpy(&u1, &h1, 2); memcpy(&u2, &h2, 2);
    return ((unsigned)u2 << 16) | u1;
}

// Device-wide barrier: monotonic release/acquire (all GRID blocks co-resident).
__device__ __forceinline__ unsigned gsync(unsigned gen) {
    __syncthreads();
    if (threadIdx.x == 0) {
        unsigned next = gen + 1u;
        unsigned old;
        asm volatile("atom.release.gpu.global.add.u32 %0, [%1], %2;"
                     : "=r"(old) : "l"(&g_bar_cnt), "r"(1u) : "memory");
        if (old == next * GRID - 1u) {
            asm volatile("st.release.gpu.global.u32 [%0], %1;"
                         :: "l"(&g_bar_gen), "r"(next) : "memory");
        } else {
            unsigned cur;
            do {
                __nanosleep(32);
                asm volatile("ld.acquire.gpu.global.u32 %0, [%1];"
                             : "=r"(cur) : "l"(&g_bar_gen) : "memory");
            } while ((int)(cur - next) < 0);
        }
    }
    __syncthreads();
    return gen + 1u;
}

// ============================================================================
// P0: convert W_out -> fragment-ordered bf16 split arrays (once)
//   frag = vt*NKT + kt ; per lane a0..a3 per m16n8k16 A-layout (row-major W)
// ============================================================================
extern "C" __global__ void __launch_bounds__(256)
p0_kernel(const float* __restrict__ W_out) {
    size_t gid = (size_t)blockIdx.x * 256 + threadIdx.x;   // < NVT*NKT*32
    int lane = (int)(gid & 31);
    size_t frag = gid >> 5;
    int kt = (int)(frag & (NKT - 1));
    size_t vt = frag >> 5;
    int g = lane >> 2, tg = lane & 3;
    size_t v0 = vt * 16 + g;
    int k0 = kt * 16 + tg * 2;
    const float* p00 = W_out + v0 * H + k0;
    float2 w00 = *reinterpret_cast<const float2*>(p00);            // a0
    float2 w01 = *reinterpret_cast<const float2*>(p00 + 8);        // a2
    float2 w10 = *reinterpret_cast<const float2*>(p00 + 8 * H);    // a1
    float2 w11 = *reinterpret_cast<const float2*>(p00 + 8 * H + 8);// a3
    uint4 f1, f2;
    cvt2(w00, f1.x, f2.x);
    cvt2(w10, f1.y, f2.y);
    cvt2(w01, f1.z, f2.z);
    cvt2(w11, f1.w, f2.w);
    g_w1f[frag * 32 + lane] = f1;
    g_w2f[frag * 32 + lane] = f2;
}

// ============================================================================
// P1: attn_x = sum_t encoder_out ; h0 = 0 ; attn output = ones ; tok0
// ============================================================================
extern "C" __global__ void p1_kernel(const float* __restrict__ enc,
                                     const int* __restrict__ y,
                                     float* __restrict__ d_out) {
    int gid  = blockIdx.x * blockDim.x + threadIdx.x;
    int nthr = gridDim.x * blockDim.x;
    if (gid < B) g_tok[gid] = y[gid * TOUT];     // y[b][0]
    for (int i = gid; i < B * H; i += nthr) {
        int b = i >> 9, k = i & 511;
        g_h[0][b][k] = 0.f;
        float s = 0.f;
        #pragma unroll 5
        for (int tt = 0; tt < TIN; tt++) s += enc[((size_t)b * TIN + tt) * H + k];
        g_attnx[b][k] = s;
    }
    float4 one4 = make_float4(1.f, 1.f, 1.f, 1.f);
    float4* dst = reinterpret_cast<float4*>(d_out + OFF_ATTN);
    size_t n4 = (size_t)TOUT * B * TIN * H / 4;
    for (size_t i = gid; i < n4; i += nthr) dst[i] = one4;
}

// ============================================================================
// MAIN persistent kernel
//   dynamic smem union:
//     A/B/prologue: inp pairs [32][257] (65792 B) + wtile[2][16][64] (16384 B)
//     C: Pw [512][36] u32 (73728 B) | wstage [8w][4st][2KB] (65536 B)
//        | zt [256][33] f32 (33792 B)   -> total 173056 B
// ============================================================================
#define S_PAD 257
#define WST_OFF 73728
#define ZT_OFF  139264
extern "C" __global__ void __launch_bounds__(256, 1)
main_kernel(const float* __restrict__ emb,
            const float* __restrict__ W_comb, const float* __restrict__ b_comb,
            const float* __restrict__ W_hh,  const float* __restrict__ b_hh,
            const float* __restrict__ W_ih,  const float* __restrict__ b_ih,
            const float* __restrict__ b_out, float* __restrict__ d_out) {
    extern __shared__ char dsm[];
    ull* inp = reinterpret_cast<ull*>(dsm);                       // A/B: [32][S_PAD]
    ull* wtile = reinterpret_cast<ull*>(dsm + 65792);             // A/B: [2][16][64]

    __shared__ int   s_tok[B];
    __shared__ float sm_m[8][B], sm_s[8][B], sm_av[8][B];
    __shared__ int   sm_ai[8][B];
    __shared__ float sp[12][33];

    int tid = threadIdx.x, bid = blockIdx.x;
    int lane = tid & 31, w = tid >> 5;
    int g = lane >> 2, tg = lane & 3;
    unsigned gen;
    asm volatile("ld.acquire.gpu.global.u32 %0, [%1];" : "=r"(gen) : "l"(&g_bar_gen));

    // ============== prologue: c_attn (blocks 0..31, A-style) ==============
    if (bid < 32) {
        int row0 = bid * 16;
        const float* wbase = W_comb + H;
        const size_t wstride = 2 * H;
        #pragma unroll
        for (int cc = 0; cc < 2; cc++) {
            #pragma unroll
            for (int p = 0; p < 2; p++) {
                int idx = p * 256 + tid;
                int r = idx >> 5, jj = idx & 31;
                cpa16(sm_u32(&wtile[(size_t)cc * 1024 + r * 64 + jj * 2]),
                      wbase + (size_t)(row0 + r) * wstride + cc * 128 + jj * 4);
            }
            asm volatile("cp.async.commit_group;");
        }
        for (int i = tid; i < B * 256; i += 256) {
            int b = i >> 8, kq = i & 255;
            float2 v = *reinterpret_cast<const float2*>(&g_attnx[b][2 * kq]);
            *reinterpret_cast<float2*>(&inp[b * S_PAD + kq]) = v;
        }
        ull a00 = 0, a01 = 0, a10 = 0, a11 = 0;
        for (int c = 0; c < 4; c++) {
            if (c < 3) asm volatile("cp.async.wait_group 1;");
            else       asm volatile("cp.async.wait_group 0;");
            __syncthreads();
            const ull* wch = wtile + (size_t)(c & 1) * 1024;
            int r0 = (2 * w) * 64, r1 = (2 * w + 1) * 64;
            const ull* xrow = inp + lane * S_PAD + c * 64;
            #pragma unroll 8
            for (int q = 0; q < 64; q += 2) {
                ull x0 = xrow[q], x1 = xrow[q + 1];
                a00 = fma2(wch[r0 + q], x0, a00);
                a01 = fma2(wch[r0 + q + 1], x1, a01);
                a10 = fma2(wch[r1 + q], x0, a10);
                a11 = fma2(wch[r1 + q + 1], x1, a11);
            }
            __syncthreads();
            if (c < 2) {
                #pragma unroll
                for (int p = 0; p < 2; p++) {
                    int idx = p * 256 + tid;
                    int r = idx >> 5, jj = idx & 31;
                    cpa16(sm_u32(&wtile[(size_t)(c & 1) * 1024 + r * 64 + jj * 2]),
                          wbase + (size_t)(row0 + r) * wstride + (c + 2) * 128 + jj * 4);
                }
                asm volatile("cp.async.commit_group;");
            }
        }
        int o0 = row0 + 2 * w;
        g_cattn[lane][o0]     = sum2(a00) + sum2(a01) + b_comb[o0];
        g_cattn[lane][o0 + 1] = sum2(a10) + sum2(a11) + b_comb[o0 + 1];
    }
    gen = gsync(gen);

    int cur = 0;
    for (int t = 0; t < TOUT; t++) {
        // ========= Phase A: (xc blocks: merge->tok) + xc / gh GEMMs =========
        {
            bool is_xc = (bid < 32);
            int row0;
            const float* wbase;
            size_t wstride;
            if (is_xc) { row0 = bid * 16; wbase = W_comb; wstride = 2 * H; }
            else       { row0 = (bid - 32) * 16; wbase = W_hh; wstride = H; }

            #pragma unroll
            for (int cc = 0; cc < 2; cc++) {
                #pragma unroll
                for (int p = 0; p < 2; p++) {
                    int idx = p * 256 + tid;
                    int r = idx >> 5, jj = idx & 31;
                    cpa16(sm_u32(&wtile[(size_t)cc * 1024 + r * 64 + jj * 2]),
                          wbase + (size_t)(row0 + r) * wstride + cc * 128 + jj * 4);
                }
                asm volatile("cp.async.commit_group;");
            }

            if (is_xc) {
                if (t > 0) {
                    int b = lane, part = w;
                    float m = -INFINITY, s = 0.f, av = -INFINITY;
                    int ai = INT_MAX;
                    for (int i = part; i < NPB; i += 8) {
                        float pm = g_pmax[i][b];
                        float ps = g_psum[i][b];
                        int   pi = g_pidx[i][b];
                        if (pm > m) { s = s * expf(m - pm) + ps; m = pm; }
                        else        { s += ps * expf(pm - m); }
                        if (pm > av || (pm == av && pi < ai)) { av = pm; ai = pi; }
                    }
                    sm_m[part][b] = m; sm_s[part][b] = s;
                    sm_av[part][b] = av; sm_ai[part][b] = ai;
                    __syncthreads();
                    if (tid < B) {
                        float M = -INFINITY, S = 0.f, AV = -INFINITY;
                        int AI = INT_MAX;
                        #pragma unroll
                        for (int p = 0; p < 8; p++) {
                            float pm = sm_m[p][tid], ps = sm_s[p][tid];
                            if (pm > M) { S = S * expf(M - pm) + ps; M = pm; }
                            else        { S += ps * expf(pm - M); }
                            float v2 = sm_av[p][tid]; int i2 = sm_ai[p][tid];
                            if (v2 > AV || (v2 == AV && i2 < AI)) { AV = v2; AI = i2; }
                        }
                        s_tok[tid] = AI;
                        if (bid == 0) g_logZ[t - 1][tid] = M + logf(S);
                    }
                } else {
                    if (tid < B) s_tok[tid] = g_tok[tid];
                }
                __syncthreads();
            }

            for (int i = tid; i < B * 256; i += 256) {
                int b = i >> 8, kq = i & 255;
                const float* src = is_xc ? (emb + (size_t)s_tok[b] * H)
                                         : &g_h[cur][b][0];
                float2 v = *reinterpret_cast<const float2*>(src + 2 * kq);
                *reinterpret_cast<float2*>(&inp[b * S_PAD + kq]) = v;
            }

            ull a00 = 0, a01 = 0, a10 = 0, a11 = 0;
            for (int c = 0; c < 4; c++) {
                if (c < 3) asm volatile("cp.async.wait_group 1;");
                else       asm volatile("cp.async.wait_group 0;");
                __syncthreads();
                const ull* wch = wtile + (size_t)(c & 1) * 1024;
                int r0 = (2 * w) * 64, r1 = (2 * w + 1) * 64;
                const ull* xrow = inp + lane * S_PAD + c * 64;
                #pragma unroll 8
                for (int q = 0; q < 64; q += 2) {
                    ull x0 = xrow[q], x1 = xrow[q + 1];
                    a00 = fma2(wch[r0 + q], x0, a00);
                    a01 = fma2(wch[r0 + q + 1], x1, a01);
                    a10 = fma2(wch[r1 + q], x0, a10);
                    a11 = fma2(wch[r1 + q + 1], x1, a11);
                }
                __syncthreads();
                if (c < 2) {
                    #pragma unroll
                    for (int p = 0; p < 2; p++) {
                        int idx = p * 256 + tid;
                        int r = idx >> 5, jj = idx & 31;
                        cpa16(sm_u32(&wtile[(size_t)(c & 1) * 1024 + r * 64 + jj * 2]),
                              wbase + (size_t)(row0 + r) * wstride + (c + 2) * 128 + jj * 4);
                    }
                    asm volatile("cp.async.commit_group;");
                }
            }
            float v0 = sum2(a00) + sum2(a01);
            float v1 = sum2(a10) + sum2(a11);
            int o0 = row0 + 2 * w, o1 = o0 + 1;
            if (is_xc) {
                v0 += g_cattn[lane][o0];
                v1 += g_cattn[lane][o1];
                g_xc[lane][o0] = v0 > 0.f ? v0 : 0.f;
                g_xc[lane][o1] = v1 > 0.f ? v1 : 0.f;
            } else {
                g_gh[lane][o0] = v0 + b_hh[o0];
                g_gh[lane][o1] = v1 + b_hh[o1];
            }
        }
        gen = gsync(gen);

        // ========= Phase B: gi (12 rows/block) + GRU + pack h =========
        {
            int obase = bid * 4;
            #pragma unroll
            for (int cc = 0; cc < 2; cc++) {
                #pragma unroll
                for (int p = 0; p < 2; p++) {
                    int idx = p * 256 + tid;
                    if (idx < 384) {
                        int r = idx >> 5, jj = idx & 31;
                        int gg = r >> 2, ol = r & 3;
                        cpa16(sm_u32(&wtile[(size_t)cc * 1024 + r * 64 + jj * 2]),
                              W_ih + (size_t)(gg * H + obase + ol) * H + cc * 128 + jj * 4);
                    }
                }
                asm volatile("cp.async.commit_group;");
            }
            for (int i = tid; i < B * 256; i += 256) {
                int b = i >> 8, kq = i & 255;
                float2 v = *reinterpret_cast<const float2*>(&g_xc[b][2 * kq]);
                *reinterpret_cast<float2*>(&inp[b * S_PAD + kq]) = v;
            }
            ull a00 = 0, a01 = 0, a10 = 0, a11 = 0;
            for (int c = 0; c < 4; c++) {
                if (c < 3) asm volatile("cp.async.wait_group 1;");
                else       asm volatile("cp.async.wait_group 0;");
                __syncthreads();
                if (w < 6) {
                    const ull* wch = wtile + (size_t)(c & 1) * 1024;
                    int r0 = (2 * w) * 64, r1 = (2 * w + 1) * 64;
                    const ull* xrow = inp + lane * S_PAD + c * 64;
                    #pragma unroll 8
                    for (int q = 0; q < 64; q += 2) {
                        ull x0 = xrow[q], x1 = xrow[q + 1];
                        a00 = fma2(wch[r0 + q], x0, a00);
                        a01 = fma2(wch[r0 + q + 1], x1, a01);
                        a10 = fma2(wch[r1 + q], x0, a10);
                        a11 = fma2(wch[r1 + q + 1], x1, a11);
                    }
                }
                __syncthreads();
                if (c < 2) {
                    #pragma unroll
                    for (int p = 0; p < 2; p++) {
                        int idx = p * 256 + tid;
                        if (idx < 384) {
                            int r = idx >> 5, jj = idx & 31;
                            int gg = r >> 2, ol = r & 3;
                            cpa16(sm_u32(&wtile[(size_t)(c & 1) * 1024 + r * 64 + jj * 2]),
                                  W_ih + (size_t)(gg * H + obase + ol) * H + (c + 2) * 128 + jj * 4);
                        }
                    }
                    asm volatile("cp.async.commit_group;");
                }
            }
            if (w < 6) {
                sp[2 * w][lane]     = sum2(a00) + sum2(a01);
                sp[2 * w + 1][lane] = sum2(a10) + sum2(a11);
            }
            __syncthreads();
            if (tid < 128) {
                int b = tid & 31, ol = tid >> 5;
                int oo = obase + ol;
                float ir  = sp[ol][b]     + b_ih[oo];
                float iz  = sp[4 + ol][b] + b_ih[oo + H];
                float inn = sp[8 + ol][b] + b_ih[oo + 2 * H];
                float r  = 1.f / (1.f + expf(-(ir + g_gh[b][oo])));
                float zz = 1.f / (1.f + expf(-(iz + g_gh[b][oo + H])));
                float n  = tanhf(inn + r * g_gh[b][oo + 2 * H]);
                float hp = g_h[cur][b][oo];
                float hn = (1.f - zz) * n + zz * hp;
                g_h[cur ^ 1][b][oo] = hn;
                g_hpk[oo * 32 + b] = pack_h(hn);
                if (t == TOUT - 1) d_out[OFF_HT + (size_t)b * H + oo] = hn;
            }
        }
        gen = gsync(gen);

        // ========= Phase C: z = h @ W_out^T + b_out via bf16x3 mma.sync =====
        //   4-stage per-warp cp.async ring for W frags (no mainloop syncs);
        //   term-outermost mma ordering (8 independent acc chains).
        if (bid < NPB) {
            unsigned* Pw = reinterpret_cast<unsigned*>(dsm);        // [512][36]
            char* wst = dsm + WST_OFF;                              // [8][4][2KB]
            float* zt = reinterpret_cast<float*>(dsm + ZT_OFF);     // [256][33]

            // stage packed h: Pw[k][36] = g_hpk[k][b]
            for (int i = tid; i < 4096; i += 256) {
                int k = i >> 3, b4 = (i & 7) * 4;
                uint4 v = *reinterpret_cast<const uint4*>(&g_hpk[k * 32 + b4]);
                *reinterpret_cast<uint4*>(&Pw[k * 36 + b4]) = v;
            }
            __syncthreads();

            size_t gvt0 = (size_t)bid * 16 + 2 * w;   // warp's first v-tile
            const uint4* W1p = g_w1f + gvt0 * NKT * 32 + lane;
            const uint4* W2p = g_w2f + gvt0 * NKT * 32 + lane;
            unsigned wsa = sm_u32(wst) + w * 8192 + lane * 16;
            const char* wrd = wst + w * 8192 + lane * 16;

            float acc[2][4][4];
            #pragma unroll
            for (int a = 0; a < 2; a++)
                #pragma unroll
                for (int bb = 0; bb < 4; bb++)
                    #pragma unroll
                    for (int cc = 0; cc < 4; cc++) acc[a][bb][cc] = 0.f;

            #pragma unroll
            for (int pre = 0; pre < 3; pre++) {
                unsigned dst = wsa + pre * 2048;
                cpa16(dst,        W1p + pre * 32);
                cpa16(dst + 512,  W2p + pre * 32);
                cpa16(dst + 1024, W1p + NKT * 32 + pre * 32);
                cpa16(dst + 1536, W2p + NKT * 32 + pre * 32);
                asm volatile("cp.async.commit_group;");
            }

            for (int kt = 0; kt < NKT; kt++) {
                if (kt + 3 < NKT) {
                    int kn = kt + 3;
                    unsigned dst = wsa + (kn & 3) * 2048;
                    cpa16(dst,        W1p + kn * 32);
                    cpa16(dst + 512,  W2p + kn * 32);
                    cpa16(dst + 1024, W1p + NKT * 32 + kn * 32);
                    cpa16(dst + 1536, W2p + NKT * 32 + kn * 32);
                    asm volatile("cp.async.commit_group;");
                    asm volatile("cp.async.wait_group 3;");
                } else if (kt == NKT - 3) {
                    asm volatile("cp.async.wait_group 2;");
                } else if (kt == NKT - 2) {
                    asm volatile("cp.async.wait_group 1;");
                } else {
                    asm volatile("cp.async.wait_group 0;");
                }

                const char* stp = wrd + (kt & 3) * 2048;
                uint4 a1c0 = *reinterpret_cast<const uint4*>(stp);
                uint4 a2c0 = *reinterpret_cast<const uint4*>(stp + 512);
                uint4 a1c1 = *reinterpret_cast<const uint4*>(stp + 1024);
                uint4 a2c1 = *reinterpret_cast<const uint4*>(stp + 1536);

                unsigned bf1[4][2], bf2[4][2];
                #pragma unroll
                for (int bt = 0; bt < 4; bt++) {
                    int n = bt * 8 + g;
                    #pragma unroll
                    for (int r = 0; r < 2; r++) {
                        int k0 = kt * 16 + tg * 2 + r * 8;
                        unsigned e0 = Pw[k0 * 36 + n];
                        unsigned e1 = Pw[(k0 + 1) * 36 + n];
                        bf1[bt][r] = prmt(e0, e1, 0x5410u);
                        bf2[bt][r] = prmt(e0, e1, 0x7632u);
                    }
                }
                // term-outermost: 8 independent accumulators between reuses
                #pragma unroll
                for (int bt = 0; bt < 4; bt++) {
                    mma16816(acc[0][bt], a1c0, bf1[bt][0], bf1[bt][1]);
                    mma16816(acc[1][bt], a1c1, bf1[bt][0], bf1[bt][1]);
                }
                #pragma unroll
                for (int bt = 0; bt < 4; bt++) {
                    mma16816(acc[0][bt], a1c0, bf2[bt][0], bf2[bt][1]);
                    mma16816(acc[1][bt], a1c1, bf2[bt][0], bf2[bt][1]);
                }
                #pragma unroll
                for (int bt = 0; bt < 4; bt++) {
                    mma16816(acc[0][bt], a2c0, bf1[bt][0], bf1[bt][1]);
                    mma16816(acc[1][bt], a2c1, bf1[bt][0], bf1[bt][1]);
                }
            }

            int vbase = bid * VPB;
            #pragma unroll
            for (int vtl = 0; vtl < 2; vtl++) {
                int lv0 = (2 * w + vtl) * 16 + g;
                float bi0 = b_out[vbase + lv0];
                float bi8 = b_out[vbase + lv0 + 8];
                #pragma unroll
                for (int bt = 0; bt < 4; bt++) {
                    int bb = bt * 8 + tg * 2;
                    zt[lv0 * 33 + bb]           = acc[vtl][bt][0] + bi0;
                    zt[lv0 * 33 + bb + 1]       = acc[vtl][bt][1] + bi0;
                    zt[(lv0 + 8) * 33 + bb]     = acc[vtl][bt][2] + bi8;
                    zt[(lv0 + 8) * 33 + bb + 1] = acc[vtl][bt][3] + bi8;
                }
            }
            __syncthreads();

            // per-(b,seg) partials: warp spans b (conflict-free column reads)
            {
                int b = tid & 31, seg = tid >> 5;
                float m = -INFINITY;
                int mi = 0;
                #pragma unroll 8
                for (int i = 0; i < 32; i++) {
                    int lv = seg * 32 + i;
                    float z = zt[lv * 33 + b];
                    if (z > m) { m = z; mi = vbase + lv; }
                }
                float s = 0.f;
                #pragma unroll 8
                for (int i = 0; i < 32; i++) {
                    int lv = seg * 32 + i;
                    s += expf(zt[lv * 33 + b] - m);
                }
                sm_m[seg][b] = m; sm_s[seg][b] = s; sm_ai[seg][b] = mi;
            }
            // coalesced v-major zbuf writeout
            for (int j = tid; j < B * VPB; j += 256) {
                int b = j >> 8, lv = j & 255;
                __stcs(&g_zbuf[((size_t)t * B + b) * V + vbase + lv],
                       zt[lv * 33 + b]);
            }
            __syncthreads();
            if (tid < B) {
                int b = tid;
                float M = -INFINITY, S = 0.f;
                int I = INT_MAX;
                #pragma unroll
                for (int p = 0; p < 8; p++) {
                    float pm = sm_m[p][b], ps = sm_s[p][b];
                    if (pm > M) { S = S * expf(M - pm) + ps; M = pm; I = sm_ai[p][b]; }
                    else        { S += ps * expf(pm - M); }
                }
                g_pmax[bid][b] = M;
                g_psum[bid][b] = S;
                g_pidx[bid][b] = I;
            }
        }
        gen = gsync(gen);
        cur ^= 1;
    }

    // ---------------- final logZ[TOUT-1] (block 0) ----------------
    if (bid == 0) {
        int b = lane, part = w;
        float m = -INFINITY, s = 0.f;
        for (int i = part; i < NPB; i += 8) {
            float pm = g_pmax[i][b], ps = g_psum[i][b];
            if (pm > m) { s = s * expf(m - pm) + ps; m = pm; }
            else        { s += ps * expf(pm - m); }
        }
        sm_m[part][b] = m; sm_s[part][b] = s;
        __syncthreads();
        if (tid < B) {
            float M = -INFINITY, S = 0.f;
            #pragma unroll
            for (int p = 0; p < 8; p++) {
                float pm = sm_m[p][tid], ps = sm_s[p][tid];
                if (pm > M) { S = S * expf(M - pm) + ps; M = pm; }
                else        { S += ps * expf(pm - M); }
            }
            g_logZ[TOUT - 1][tid] = M + logf(S);
        }
    }
}

// ============================================================================
// E2: out[b][v][t] = z[t][b][v] - logZ[t][b]   (smem-tiled transpose)
// ============================================================================
extern "C" __global__ void __launch_bounds__(256)
e2_kernel(float* __restrict__ d_out) {
    __shared__ float s_z[128][52];
    __shared__ float s_lz[TOUT];
    int b = blockIdx.y;
    int v0 = blockIdx.x * 128;
    int tid = threadIdx.x;
    if (tid < TOUT) s_lz[tid] = g_logZ[tid][b];
    __syncthreads();
    for (int j = tid; j < 128 * TOUT; j += 256) {
        int tt = j >> 7, vl = j & 127;
        s_z[vl][tt] = __ldcs(&g_zbuf[((size_t)tt * B + b) * V + v0 + vl]) - s_lz[tt];
    }
    __syncthreads();
    size_t base = ((size_t)b * V + v0) * TOUT;
    for (int j = tid; j < 128 * TOUT; j += 256) {
        int vl = j / TOUT, tt = j % TOUT;
        d_out[base + j] = s_z[vl][tt];
    }
}

// ============================================================================
extern "C" void kernel_launch(void* const* d_in, const int* in_sizes, int n_in,
                              void* d_out_v, int out_size) {
    const float* enc    = (const float*)d_in[0];
    const int*   y      = (const int*)d_in[1];
    const float* emb    = (const float*)d_in[2];
    // d_in[3..6]: W_fc, b_fc, W_fc1, W_fc2 — dead (softmax over singleton axis)
    const float* W_comb = (const float*)d_in[7];
    const float* b_comb = (const float*)d_in[8];
    const float* W_ih   = (const float*)d_in[9];
    const float* W_hh   = (const float*)d_in[10];
    const float* b_ih   = (const float*)d_in[11];
    const float* b_hh   = (const float*)d_in[12];
    const float* W_out  = (const float*)d_in[13];
    const float* b_out  = (const float*)d_in[14];
    float* d_out = (float*)d_out_v;

    const int main_smem = ZT_OFF + 256 * 33 * 4;   // 173056 (covers A/B's 82176)
    cudaFuncSetAttribute(main_kernel, cudaFuncAttributeMaxDynamicSharedMemorySize,
                         main_smem);

    p0_kernel<<<(NVT * NKT * 32) / 256, 256>>>(W_out);
    p1_kernel<<<512, 256>>>(enc, y, d_out);
    main_kernel<<<GRID, 256, main_smem>>>(emb, W_comb, b_comb, W_hh, b_hh,
                                          W_ih, b_ih, b_out, d_out);
    e2_kernel<<<dim3(V / 128, B), 256>>>(d_out);
}